// round 2
// baseline (speedup 1.0000x reference)
#include <cuda_runtime.h>
#include <math.h>

// Problem constants
#define Bc   16
#define Sc   512
#define Vc   512
#define Hc   1024
#define NLc  8
#define NHc  16
#define DHc  64
#define Fc   4096
#define Mrows (Bc*Sc)   // 8192 token rows

// ---------------- scratch (static device memory; no runtime allocs) ----------------
__device__ float g_x   [(size_t)Mrows*Hc];        // residual stream
__device__ float g_h   [(size_t)Mrows*Hc];        // LN output
__device__ float g_qkv [(size_t)Mrows*3*Hc];      // fused qkv
__device__ float g_scr [(size_t)Bc*NHc*Sc*Sc];    // attention scores / probs
__device__ float g_attn[(size_t)Mrows*Hc];        // attention output (B,S,H)
__device__ float g_ffn [(size_t)Mrows*Fc];        // ffn intermediate

// ---------------- embedding gather ----------------
__global__ void embed_kernel(const int* __restrict__ ids,
                             const float* __restrict__ emb,
                             float* __restrict__ out) {
    int t = blockIdx.x;
    int id = ids[t];
    const float4* src = (const float4*)(emb + (size_t)id * Hc);
    float4* dst = (float4*)(out + (size_t)t * Hc);
    dst[threadIdx.x] = src[threadIdx.x];   // 256 threads * 4 = 1024
}

// ---------------- layernorm (one block per row, 256 threads) ----------------
__global__ void ln_kernel(const float* __restrict__ x,
                          const float* __restrict__ g,
                          const float* __restrict__ b,
                          float* __restrict__ out) {
    __shared__ float s1[256], s2[256];
    int row = blockIdx.x, tid = threadIdx.x;
    float4 v = ((const float4*)(x + (size_t)row * Hc))[tid];
    s1[tid] = v.x + v.y + v.z + v.w;
    s2[tid] = v.x*v.x + v.y*v.y + v.z*v.z + v.w*v.w;
    __syncthreads();
    for (int s = 128; s > 0; s >>= 1) {
        if (tid < s) { s1[tid] += s1[tid+s]; s2[tid] += s2[tid+s]; }
        __syncthreads();
    }
    float mu  = s1[0] * (1.0f / Hc);
    float var = s2[0] * (1.0f / Hc) - mu * mu;
    float inv = rsqrtf(var + 1e-5f);
    float4 gg = ((const float4*)g)[tid];
    float4 bb = ((const float4*)b)[tid];
    float4 o;
    o.x = (v.x - mu) * inv * gg.x + bb.x;
    o.y = (v.y - mu) * inv * gg.y + bb.y;
    o.z = (v.z - mu) * inv * gg.z + bb.z;
    o.w = (v.w - mu) * inv * gg.w + bb.w;
    ((float4*)(out + (size_t)row * Hc))[tid] = o;
}

// ---------------- gelu (tanh approximation) ----------------
__device__ __forceinline__ float gelu_f(float x) {
    float x3 = x * x * x;
    return 0.5f * x * (1.0f + tanhf(0.7978845608028654f * (x + 0.044715f * x3)));
}

// ---------------- generic fp32 GEMM: C = act(A@W + bias) (+= residual C) ----------------
// 128x128 block tile, BK=8, 256 threads, 8x8 per thread.
// TRANSB: W indexed as W[n*K + k] (for logits @ emb^T)
template<bool TRANSB, bool RES, bool GELU_ACT, bool BIAS>
__global__ __launch_bounds__(256)
void gemm128(const float* __restrict__ A, const float* __restrict__ W,
             const float* __restrict__ bias, float* __restrict__ C,
             int M, int N, int K) {
    __shared__ float As[8][128];
    __shared__ float Ws[8][128];
    int tid = threadIdx.x;
    int m0 = blockIdx.y * 128, n0 = blockIdx.x * 128;
    int tx = tid & 15, ty = tid >> 4;

    float acc[8][8];
    #pragma unroll
    for (int i = 0; i < 8; ++i)
        #pragma unroll
        for (int j = 0; j < 8; ++j) acc[i][j] = 0.f;

    int arow = tid >> 1;         // 0..127
    int acol = (tid & 1) * 4;    // 0 or 4

    for (int k0 = 0; k0 < K; k0 += 8) {
        // A tile -> transposed into As[k][m]
        float4 av = *(const float4*)&A[(size_t)(m0 + arow) * K + k0 + acol];
        As[acol+0][arow] = av.x; As[acol+1][arow] = av.y;
        As[acol+2][arow] = av.z; As[acol+3][arow] = av.w;
        if (!TRANSB) {
            int wr = tid >> 5;            // 0..7
            int wc = (tid & 31) * 4;      // 0..124
            float4 wv = *(const float4*)&W[(size_t)(k0 + wr) * N + n0 + wc];
            *(float4*)&Ws[wr][wc] = wv;
        } else {
            int nr = tid >> 1;            // 0..127
            int kc = (tid & 1) * 4;       // 0 or 4
            float4 wv = *(const float4*)&W[(size_t)(n0 + nr) * K + k0 + kc];
            Ws[kc+0][nr] = wv.x; Ws[kc+1][nr] = wv.y;
            Ws[kc+2][nr] = wv.z; Ws[kc+3][nr] = wv.w;
        }
        __syncthreads();
        #pragma unroll
        for (int kk = 0; kk < 8; ++kk) {
            float ra[8], rb[8];
            *(float4*)&ra[0] = *(float4*)&As[kk][ty*8];
            *(float4*)&ra[4] = *(float4*)&As[kk][ty*8+4];
            *(float4*)&rb[0] = *(float4*)&Ws[kk][tx*8];
            *(float4*)&rb[4] = *(float4*)&Ws[kk][tx*8+4];
            #pragma unroll
            for (int i = 0; i < 8; ++i)
                #pragma unroll
                for (int j = 0; j < 8; ++j)
                    acc[i][j] += ra[i] * rb[j];
        }
        __syncthreads();
    }

    #pragma unroll
    for (int i = 0; i < 8; ++i) {
        int m = m0 + ty*8 + i;
        #pragma unroll
        for (int j = 0; j < 8; ++j) {
            int n = n0 + tx*8 + j;
            float v = acc[i][j];
            if (BIAS)     v += bias[n];
            if (GELU_ACT) v = gelu_f(v);
            float* cp = &C[(size_t)m * N + n];
            if (RES) v += *cp;
            *cp = v;
        }
    }
}

// ---------------- attention scores: q@k^T * scale + alibi/mask ----------------
// grid: (S/64 [j], S/64 [i], B*NH), 256 threads, 4x4 per thread
__global__ __launch_bounds__(256)
void scores_kernel(const float* __restrict__ qkv, const int* __restrict__ sp,
                   float* __restrict__ scores) {
    int bz = blockIdx.z;
    int b = bz >> 4, n = bz & 15;
    int i0 = blockIdx.y * 64, j0 = blockIdx.x * 64;
    __shared__ float Qs[16][64], Ks[16][64];
    int tid = threadIdx.x;
    int tx = tid & 15, ty = tid >> 4;
    float acc[4][4] = {};
    const float* qbase = qkv + (size_t)b * Sc * 3 * Hc + n * DHc;
    const float* kbase = qbase + Hc;
    int lr = tid >> 2;          // 0..63
    int lc = (tid & 3) * 4;     // 0,4,8,12

    for (int k0 = 0; k0 < DHc; k0 += 16) {
        float4 qv = *(const float4*)&qbase[(size_t)(i0 + lr) * 3 * Hc + k0 + lc];
        Qs[lc+0][lr] = qv.x; Qs[lc+1][lr] = qv.y; Qs[lc+2][lr] = qv.z; Qs[lc+3][lr] = qv.w;
        float4 kv = *(const float4*)&kbase[(size_t)(j0 + lr) * 3 * Hc + k0 + lc];
        Ks[lc+0][lr] = kv.x; Ks[lc+1][lr] = kv.y; Ks[lc+2][lr] = kv.z; Ks[lc+3][lr] = kv.w;
        __syncthreads();
        #pragma unroll
        for (int kk = 0; kk < 16; ++kk) {
            float ra[4], rb[4];
            *(float4*)&ra[0] = *(float4*)&Qs[kk][ty*4];
            *(float4*)&rb[0] = *(float4*)&Ks[kk][tx*4];
            #pragma unroll
            for (int i = 0; i < 4; ++i)
                #pragma unroll
                for (int j = 0; j < 4; ++j)
                    acc[i][j] += ra[i] * rb[j];
        }
        __syncthreads();
    }

    int spb = sp[b];
    float slope = exp2f(-0.5f * (float)(n + 1));
    #pragma unroll
    for (int ii = 0; ii < 4; ++ii) {
        int i = i0 + ty*4 + ii;
        #pragma unroll
        for (int jj = 0; jj < 4; ++jj) {
            int j = j0 + tx*4 + jj;
            bool allowed = (j <= i) && !((i >= spb) && (j < spb));
            float val = allowed ? (acc[ii][jj] * 0.125f - slope * (float)(i - j))
                                : -1e9f;
            scores[((size_t)bz * Sc + i) * Sc + j] = val;
        }
    }
}

// ---------------- row softmax over S=512 (128 threads x 4) ----------------
__global__ void softmax_kernel(float* __restrict__ scores) {
    __shared__ float sh[128];
    size_t row = blockIdx.x;
    float* p = scores + row * (size_t)Sc;
    int tid = threadIdx.x;
    float4 v = ((float4*)p)[tid];
    float mx = fmaxf(fmaxf(v.x, v.y), fmaxf(v.z, v.w));
    sh[tid] = mx; __syncthreads();
    for (int s = 64; s > 0; s >>= 1) {
        if (tid < s) sh[tid] = fmaxf(sh[tid], sh[tid+s]);
        __syncthreads();
    }
    mx = sh[0]; __syncthreads();
    v.x = expf(v.x - mx); v.y = expf(v.y - mx);
    v.z = expf(v.z - mx); v.w = expf(v.w - mx);
    sh[tid] = v.x + v.y + v.z + v.w; __syncthreads();
    for (int s = 64; s > 0; s >>= 1) {
        if (tid < s) sh[tid] += sh[tid+s];
        __syncthreads();
    }
    float inv = 1.0f / sh[0];
    v.x *= inv; v.y *= inv; v.z *= inv; v.w *= inv;
    ((float4*)p)[tid] = v;
}

// ---------------- attention A = P @ V ----------------
// grid: (S/64 [i], 1, B*NH); tile 64(i) x 64(d), K=S in steps of 16
__global__ __launch_bounds__(256)
void av_kernel(const float* __restrict__ scores, const float* __restrict__ qkv,
               float* __restrict__ out) {
    int bz = blockIdx.z;
    int b = bz >> 4, n = bz & 15;
    int i0 = blockIdx.x * 64;
    __shared__ float Ps[16][64], Vs[16][64];
    int tid = threadIdx.x;
    int tx = tid & 15, ty = tid >> 4;
    float acc[4][4] = {};
    const float* prow  = scores + ((size_t)bz * Sc + i0) * Sc;
    const float* vbase = qkv + (size_t)b * Sc * 3 * Hc + 2 * Hc + n * DHc;
    int lr = tid >> 2, lc = (tid & 3) * 4;     // P load: 64 rows x 16 cols
    int vr = tid >> 4, vc = (tid & 15) * 4;    // V load: 16 rows x 64 cols

    for (int j0 = 0; j0 < Sc; j0 += 16) {
        float4 pv = *(const float4*)&prow[(size_t)lr * Sc + j0 + lc];
        Ps[lc+0][lr] = pv.x; Ps[lc+1][lr] = pv.y; Ps[lc+2][lr] = pv.z; Ps[lc+3][lr] = pv.w;
        float4 vv = *(const float4*)&vbase[(size_t)(j0 + vr) * 3 * Hc + vc];
        *(float4*)&Vs[vr][vc] = vv;
        __syncthreads();
        #pragma unroll
        for (int kk = 0; kk < 16; ++kk) {
            float ra[4], rb[4];
            *(float4*)&ra[0] = *(float4*)&Ps[kk][ty*4];
            *(float4*)&rb[0] = *(float4*)&Vs[kk][tx*4];
            #pragma unroll
            for (int i = 0; i < 4; ++i)
                #pragma unroll
                for (int j = 0; j < 4; ++j)
                    acc[i][j] += ra[i] * rb[j];
        }
        __syncthreads();
    }

    #pragma unroll
    for (int ii = 0; ii < 4; ++ii) {
        int i = i0 + ty*4 + ii;
        #pragma unroll
        for (int jj = 0; jj < 4; ++jj) {
            int d = tx*4 + jj;
            out[(size_t)(b * Sc + i) * Hc + n * DHc + d] = acc[ii][jj];
        }
    }
}

// ---------------- launch ----------------
extern "C" void kernel_launch(void* const* d_in, const int* in_sizes, int n_in,
                              void* d_out, int out_size) {
    const int*   ids    = (const int*)d_in[0];
    const int*   sp     = (const int*)d_in[1];
    const float* emb    = (const float*)d_in[2];
    const float* ln1_g  = (const float*)d_in[3];
    const float* ln1_b  = (const float*)d_in[4];
    const float* Wqkv   = (const float*)d_in[5];
    const float* bqkv   = (const float*)d_in[6];
    const float* Wo     = (const float*)d_in[7];
    const float* bo     = (const float*)d_in[8];
    const float* ln2_g  = (const float*)d_in[9];
    const float* ln2_b  = (const float*)d_in[10];
    const float* Wfc    = (const float*)d_in[11];
    const float* bfc    = (const float*)d_in[12];
    const float* Wproj  = (const float*)d_in[13];
    const float* bproj  = (const float*)d_in[14];
    const float* lnf_g  = (const float*)d_in[15];
    const float* lnf_b  = (const float*)d_in[16];
    float* out = (float*)d_out;

    float *x, *h, *qkv, *scr, *attn, *ffn;
    cudaGetSymbolAddress((void**)&x,    g_x);
    cudaGetSymbolAddress((void**)&h,    g_h);
    cudaGetSymbolAddress((void**)&qkv,  g_qkv);
    cudaGetSymbolAddress((void**)&scr,  g_scr);
    cudaGetSymbolAddress((void**)&attn, g_attn);
    cudaGetSymbolAddress((void**)&ffn,  g_ffn);

    embed_kernel<<<Mrows, 256>>>(ids, emb, x);

    for (int l = 0; l < NLc; ++l) {
        // h = LN1(x)
        ln_kernel<<<Mrows, 256>>>(x, ln1_g + (size_t)l*Hc, ln1_b + (size_t)l*Hc, h);
        // qkv = h @ Wqkv + bqkv
        gemm128<false,false,false,true><<<dim3(3*Hc/128, Mrows/128), 256>>>(
            h, Wqkv + (size_t)l*Hc*3*Hc, bqkv + (size_t)l*3*Hc, qkv, Mrows, 3*Hc, Hc);
        // scores (+ alibi + masking)
        scores_kernel<<<dim3(Sc/64, Sc/64, Bc*NHc), 256>>>(qkv, sp, scr);
        // softmax
        softmax_kernel<<<Bc*NHc*Sc, 128>>>(scr);
        // attn = P @ V
        av_kernel<<<dim3(Sc/64, 1, Bc*NHc), 256>>>(scr, qkv, attn);
        // x += attn @ Wo + bo
        gemm128<false,true,false,true><<<dim3(Hc/128, Mrows/128), 256>>>(
            attn, Wo + (size_t)l*Hc*Hc, bo + (size_t)l*Hc, x, Mrows, Hc, Hc);
        // h = LN2(x)
        ln_kernel<<<Mrows, 256>>>(x, ln2_g + (size_t)l*Hc, ln2_b + (size_t)l*Hc, h);
        // ffn = gelu(h @ Wfc + bfc)
        gemm128<false,false,true,true><<<dim3(Fc/128, Mrows/128), 256>>>(
            h, Wfc + (size_t)l*Hc*Fc, bfc + (size_t)l*Fc, ffn, Mrows, Fc, Hc);
        // x += ffn @ Wproj + bproj
        gemm128<false,true,false,true><<<dim3(Hc/128, Mrows/128), 256>>>(
            ffn, Wproj + (size_t)l*Fc*Hc, bproj + (size_t)l*Hc, x, Mrows, Hc, Fc);
    }

    // final LN + logits = h @ emb^T
    ln_kernel<<<Mrows, 256>>>(x, lnf_g, lnf_b, h);
    gemm128<true,false,false,false><<<dim3(Vc/128, Mrows/128), 256>>>(
        h, emb, nullptr, out, Mrows, Vc, Hc);
}

// round 3
// speedup vs baseline: 2.1150x; 2.1150x over previous
#include <cuda_runtime.h>
#include <math.h>
#include <stdint.h>

// Problem constants
#define Bc   16
#define Sc   512
#define Vc   512
#define Hc   1024
#define NLc  8
#define NHc  16
#define DHc  64
#define Fc   4096
#define Mrows (Bc*Sc)   // 8192 token rows

// ---------------- scratch (static device memory; no runtime allocs) ----------------
__device__ float g_x   [(size_t)Mrows*Hc];        // residual stream
__device__ float g_h   [(size_t)Mrows*Hc];        // LN output
__device__ float g_qkv [(size_t)Mrows*3*Hc];      // fused qkv
__device__ float g_scr [(size_t)Bc*NHc*Sc*Sc];    // attention scores / probs
__device__ float g_attn[(size_t)Mrows*Hc];        // attention output (B,S,H)
__device__ float g_ffn [(size_t)Mrows*Fc];        // ffn intermediate

// ---------------- embedding gather ----------------
__global__ void embed_kernel(const int* __restrict__ ids,
                             const float* __restrict__ emb,
                             float* __restrict__ out) {
    int t = blockIdx.x;
    int id = ids[t];
    const float4* src = (const float4*)(emb + (size_t)id * Hc);
    float4* dst = (float4*)(out + (size_t)t * Hc);
    dst[threadIdx.x] = src[threadIdx.x];   // 256 threads * 4 = 1024
}

// ---------------- layernorm (one block per row, 256 threads) ----------------
__global__ void ln_kernel(const float* __restrict__ x,
                          const float* __restrict__ g,
                          const float* __restrict__ b,
                          float* __restrict__ out) {
    __shared__ float s1[256], s2[256];
    int row = blockIdx.x, tid = threadIdx.x;
    float4 v = ((const float4*)(x + (size_t)row * Hc))[tid];
    s1[tid] = v.x + v.y + v.z + v.w;
    s2[tid] = v.x*v.x + v.y*v.y + v.z*v.z + v.w*v.w;
    __syncthreads();
    for (int s = 128; s > 0; s >>= 1) {
        if (tid < s) { s1[tid] += s1[tid+s]; s2[tid] += s2[tid+s]; }
        __syncthreads();
    }
    float mu  = s1[0] * (1.0f / Hc);
    float var = s2[0] * (1.0f / Hc) - mu * mu;
    float inv = rsqrtf(var + 1e-5f);
    float4 gg = ((const float4*)g)[tid];
    float4 bb = ((const float4*)b)[tid];
    float4 o;
    o.x = (v.x - mu) * inv * gg.x + bb.x;
    o.y = (v.y - mu) * inv * gg.y + bb.y;
    o.z = (v.z - mu) * inv * gg.z + bb.z;
    o.w = (v.w - mu) * inv * gg.w + bb.w;
    ((float4*)(out + (size_t)row * Hc))[tid] = o;
}

// ---------------- gelu (tanh approximation) ----------------
__device__ __forceinline__ float gelu_f(float x) {
    float x3 = x * x * x;
    return 0.5f * x * (1.0f + tanhf(0.7978845608028654f * (x + 0.044715f * x3)));
}

// ---------------- tf32 helpers ----------------
__device__ __forceinline__ uint32_t f2tf(float f) {
    uint32_t u;
    asm("cvt.rna.tf32.f32 %0, %1;" : "=r"(u) : "f"(f));
    return u;
}

__device__ __forceinline__ void mma_tf32(float c[4],
                                         uint32_t a0, uint32_t a1, uint32_t a2, uint32_t a3,
                                         uint32_t b0, uint32_t b1) {
    asm volatile(
        "mma.sync.aligned.m16n8k8.row.col.f32.tf32.tf32.f32 "
        "{%0,%1,%2,%3}, {%4,%5,%6,%7}, {%8,%9}, {%0,%1,%2,%3};"
        : "+f"(c[0]), "+f"(c[1]), "+f"(c[2]), "+f"(c[3])
        : "r"(a0), "r"(a1), "r"(a2), "r"(a3), "r"(b0), "r"(b1));
}

// ---------------- tf32 tensor-core GEMM: C = act(A@W + bias) (+= residual C) ----------
// Block tile 128x128, BK=16, 256 threads (8 warps, 2x4), warp tile 64x32.
// A smem: fragment-blocked layout idx(k,m) = (k>>2)*512 + (m>>3)*32 + (m&7)*4 + (k&3)
//   -> STS.128 friendly, fragment LDS conflict-free.
// B smem (!TRANSB): XOR layout idx(k,n) = k*128 + (n ^ ((k&3)<<3))
// B smem (TRANSB): same blocked layout as A (roles m->n).
template<bool TRANSB, bool RES, bool GELU_ACT, bool BIAS>
__global__ __launch_bounds__(256)
void gemm_tc(const float* __restrict__ A, const float* __restrict__ W,
             const float* __restrict__ bias, float* __restrict__ C,
             int M, int N, int K) {
    __shared__ uint32_t As[2][2048];
    __shared__ uint32_t Bs[2][2048];

    int tid  = threadIdx.x;
    int lane = tid & 31;
    int warp = tid >> 5;
    int m0 = blockIdx.y * 128, n0 = blockIdx.x * 128;
    int warpM = (warp >> 2) * 64;
    int warpN = (warp & 3) * 32;

    float acc[4][4][4];
    #pragma unroll
    for (int i = 0; i < 4; ++i)
        #pragma unroll
        for (int j = 0; j < 4; ++j)
            #pragma unroll
            for (int r = 0; r < 4; ++r) acc[i][j][r] = 0.f;

    // ---- global load mapping ----
    int arow = tid >> 1;          // 0..127
    int akc  = (tid & 1) * 8;     // 0 or 8
    const float* Aptr = A + (size_t)(m0 + arow) * K + akc;
    int aSts = (akc >> 2) * 512 + (arow >> 3) * 32 + (arow & 7) * 4;

    const float* Wptr;
    int bSts;
    if (TRANSB) {
        int brow = tid >> 1;      // n index 0..127
        int bkc  = (tid & 1) * 8;
        Wptr = W + (size_t)(n0 + brow) * K + bkc;
        bSts = (bkc >> 2) * 512 + (brow >> 3) * 32 + (brow & 7) * 4;
    } else {
        int brow = tid >> 4;          // k row 0..15
        int bcol = (tid & 15) * 8;    // n 0..120
        Wptr = W + (size_t)brow * N + n0 + bcol;
        bSts = brow * 128 + (bcol ^ ((brow & 3) << 3));
    }

    float4 aR0, aR1, bR0, bR1;

    auto ldg = [&]() {
        aR0 = *(const float4*)(Aptr);
        aR1 = *(const float4*)(Aptr + 4);
        bR0 = *(const float4*)(Wptr);
        bR1 = *(const float4*)(Wptr + 4);
    };

    auto sts = [&](int buf) {
        uint4 u;
        u.x = f2tf(aR0.x); u.y = f2tf(aR0.y); u.z = f2tf(aR0.z); u.w = f2tf(aR0.w);
        *(uint4*)&As[buf][aSts] = u;
        u.x = f2tf(aR1.x); u.y = f2tf(aR1.y); u.z = f2tf(aR1.z); u.w = f2tf(aR1.w);
        *(uint4*)&As[buf][aSts + 512] = u;
        u.x = f2tf(bR0.x); u.y = f2tf(bR0.y); u.z = f2tf(bR0.z); u.w = f2tf(bR0.w);
        *(uint4*)&Bs[buf][bSts] = u;
        u.x = f2tf(bR1.x); u.y = f2tf(bR1.y); u.z = f2tf(bR1.z); u.w = f2tf(bR1.w);
        if (TRANSB) *(uint4*)&Bs[buf][bSts + 512] = u;   // k+4
        else        *(uint4*)&Bs[buf][bSts + 4]   = u;   // n+4 within 8-chunk
    };

    auto compute = [&](int buf) {
        #pragma unroll
        for (int ks = 0; ks < 2; ++ks) {
            int kk = ks * 8;
            uint32_t af[4][4], bf[4][2];
            #pragma unroll
            for (int mf = 0; mf < 4; ++mf) {
                int base = (kk >> 2) * 512 + ((warpM + mf * 16) >> 3) * 32 + lane;
                af[mf][0] = As[buf][base];
                af[mf][1] = As[buf][base + 32];   // m+8
                af[mf][2] = As[buf][base + 512];  // k+4
                af[mf][3] = As[buf][base + 544];
            }
            #pragma unroll
            for (int nf = 0; nf < 4; ++nf) {
                int nb = warpN + nf * 8;
                if (TRANSB) {
                    int base = (kk >> 2) * 512 + (nb >> 3) * 32 + lane;
                    bf[nf][0] = Bs[buf][base];
                    bf[nf][1] = Bs[buf][base + 512];   // k+4
                } else {
                    int k = kk + (lane & 3);
                    int addr = k * 128 + ((nb + (lane >> 2)) ^ ((lane & 3) << 3));
                    bf[nf][0] = Bs[buf][addr];
                    bf[nf][1] = Bs[buf][addr + 512];   // k+4 (same xor)
                }
            }
            #pragma unroll
            for (int mf = 0; mf < 4; ++mf)
                #pragma unroll
                for (int nf = 0; nf < 4; ++nf)
                    mma_tf32(acc[mf][nf], af[mf][0], af[mf][1], af[mf][2], af[mf][3],
                             bf[nf][0], bf[nf][1]);
        }
    };

    // ---- main loop, double buffered ----
    int nIter = K >> 4;
    ldg();
    sts(0);
    __syncthreads();
    for (int it = 0; it < nIter; ++it) {
        int cur = it & 1;
        if (it + 1 < nIter) {
            Aptr += 16;
            if (TRANSB) Wptr += 16;
            else        Wptr += (size_t)16 * N;
            ldg();
        }
        compute(cur);
        if (it + 1 < nIter) sts(cur ^ 1);
        __syncthreads();
    }

    // ---- epilogue ----
    int rbase = m0 + warpM + (lane >> 2);
    int cbase = n0 + warpN + (lane & 3) * 2;
    #pragma unroll
    for (int mf = 0; mf < 4; ++mf) {
        #pragma unroll
        for (int nf = 0; nf < 4; ++nf) {
            int c = cbase + nf * 8;
            float bx = 0.f, by = 0.f;
            if (BIAS) { bx = bias[c]; by = bias[c + 1]; }
            #pragma unroll
            for (int half = 0; half < 2; ++half) {
                int r = rbase + mf * 16 + half * 8;
                float v0 = acc[mf][nf][half * 2 + 0] + bx;
                float v1 = acc[mf][nf][half * 2 + 1] + by;
                if (GELU_ACT) { v0 = gelu_f(v0); v1 = gelu_f(v1); }
                float2* cp = (float2*)&C[(size_t)r * N + c];
                if (RES) { float2 old = *cp; v0 += old.x; v1 += old.y; }
                float2 o; o.x = v0; o.y = v1;
                *cp = o;
            }
        }
    }
}

// ---------------- attention scores: q@k^T * scale + alibi/mask ----------------
// grid: (S/64 [j], S/64 [i], B*NH), 256 threads, 4x4 per thread
__global__ __launch_bounds__(256)
void scores_kernel(const float* __restrict__ qkv, const int* __restrict__ sp,
                   float* __restrict__ scores) {
    int bz = blockIdx.z;
    int b = bz >> 4, n = bz & 15;
    int i0 = blockIdx.y * 64, j0 = blockIdx.x * 64;
    __shared__ float Qs[16][64], Ks[16][64];
    int tid = threadIdx.x;
    int tx = tid & 15, ty = tid >> 4;
    float acc[4][4] = {};
    const float* qbase = qkv + (size_t)b * Sc * 3 * Hc + n * DHc;
    const float* kbase = qbase + Hc;
    int lr = tid >> 2;          // 0..63
    int lc = (tid & 3) * 4;     // 0,4,8,12

    for (int k0 = 0; k0 < DHc; k0 += 16) {
        float4 qv = *(const float4*)&qbase[(size_t)(i0 + lr) * 3 * Hc + k0 + lc];
        Qs[lc+0][lr] = qv.x; Qs[lc+1][lr] = qv.y; Qs[lc+2][lr] = qv.z; Qs[lc+3][lr] = qv.w;
        float4 kv = *(const float4*)&kbase[(size_t)(j0 + lr) * 3 * Hc + k0 + lc];
        Ks[lc+0][lr] = kv.x; Ks[lc+1][lr] = kv.y; Ks[lc+2][lr] = kv.z; Ks[lc+3][lr] = kv.w;
        __syncthreads();
        #pragma unroll
        for (int kk = 0; kk < 16; ++kk) {
            float ra[4], rb[4];
            *(float4*)&ra[0] = *(float4*)&Qs[kk][ty*4];
            *(float4*)&rb[0] = *(float4*)&Ks[kk][tx*4];
            #pragma unroll
            for (int i = 0; i < 4; ++i)
                #pragma unroll
                for (int j = 0; j < 4; ++j)
                    acc[i][j] += ra[i] * rb[j];
        }
        __syncthreads();
    }

    int spb = sp[b];
    float slope = exp2f(-0.5f * (float)(n + 1));
    #pragma unroll
    for (int ii = 0; ii < 4; ++ii) {
        int i = i0 + ty*4 + ii;
        #pragma unroll
        for (int jj = 0; jj < 4; ++jj) {
            int j = j0 + tx*4 + jj;
            bool allowed = (j <= i) && !((i >= spb) && (j < spb));
            float val = allowed ? (acc[ii][jj] * 0.125f - slope * (float)(i - j))
                                : -1e9f;
            scores[((size_t)bz * Sc + i) * Sc + j] = val;
        }
    }
}

// ---------------- row softmax over S=512 (128 threads x 4) ----------------
__global__ void softmax_kernel(float* __restrict__ scores) {
    __shared__ float sh[128];
    size_t row = blockIdx.x;
    float* p = scores + row * (size_t)Sc;
    int tid = threadIdx.x;
    float4 v = ((float4*)p)[tid];
    float mx = fmaxf(fmaxf(v.x, v.y), fmaxf(v.z, v.w));
    sh[tid] = mx; __syncthreads();
    for (int s = 64; s > 0; s >>= 1) {
        if (tid < s) sh[tid] = fmaxf(sh[tid], sh[tid+s]);
        __syncthreads();
    }
    mx = sh[0]; __syncthreads();
    v.x = expf(v.x - mx); v.y = expf(v.y - mx);
    v.z = expf(v.z - mx); v.w = expf(v.w - mx);
    sh[tid] = v.x + v.y + v.z + v.w; __syncthreads();
    for (int s = 64; s > 0; s >>= 1) {
        if (tid < s) sh[tid] += sh[tid+s];
        __syncthreads();
    }
    float inv = 1.0f / sh[0];
    v.x *= inv; v.y *= inv; v.z *= inv; v.w *= inv;
    ((float4*)p)[tid] = v;
}

// ---------------- attention A = P @ V ----------------
// grid: (S/64 [i], 1, B*NH); tile 64(i) x 64(d), K=S in steps of 16
__global__ __launch_bounds__(256)
void av_kernel(const float* __restrict__ scores, const float* __restrict__ qkv,
               float* __restrict__ out) {
    int bz = blockIdx.z;
    int b = bz >> 4, n = bz & 15;
    int i0 = blockIdx.x * 64;
    __shared__ float Ps[16][64], Vs[16][64];
    int tid = threadIdx.x;
    int tx = tid & 15, ty = tid >> 4;
    float acc[4][4] = {};
    const float* prow  = scores + ((size_t)bz * Sc + i0) * Sc;
    const float* vbase = qkv + (size_t)b * Sc * 3 * Hc + 2 * Hc + n * DHc;
    int lr = tid >> 2, lc = (tid & 3) * 4;     // P load: 64 rows x 16 cols
    int vr = tid >> 4, vc = (tid & 15) * 4;    // V load: 16 rows x 64 cols

    for (int j0 = 0; j0 < Sc; j0 += 16) {
        float4 pv = *(const float4*)&prow[(size_t)lr * Sc + j0 + lc];
        Ps[lc+0][lr] = pv.x; Ps[lc+1][lr] = pv.y; Ps[lc+2][lr] = pv.z; Ps[lc+3][lr] = pv.w;
        float4 vv = *(const float4*)&vbase[(size_t)(j0 + vr) * 3 * Hc + vc];
        *(float4*)&Vs[vr][vc] = vv;
        __syncthreads();
        #pragma unroll
        for (int kk = 0; kk < 16; ++kk) {
            float ra[4], rb[4];
            *(float4*)&ra[0] = *(float4*)&Ps[kk][ty*4];
            *(float4*)&rb[0] = *(float4*)&Vs[kk][tx*4];
            #pragma unroll
            for (int i = 0; i < 4; ++i)
                #pragma unroll
                for (int j = 0; j < 4; ++j)
                    acc[i][j] += ra[i] * rb[j];
        }
        __syncthreads();
    }

    #pragma unroll
    for (int ii = 0; ii < 4; ++ii) {
        int i = i0 + ty*4 + ii;
        #pragma unroll
        for (int jj = 0; jj < 4; ++jj) {
            int d = tx*4 + jj;
            out[(size_t)(b * Sc + i) * Hc + n * DHc + d] = acc[ii][jj];
        }
    }
}

// ---------------- launch ----------------
extern "C" void kernel_launch(void* const* d_in, const int* in_sizes, int n_in,
                              void* d_out, int out_size) {
    const int*   ids    = (const int*)d_in[0];
    const int*   sp     = (const int*)d_in[1];
    const float* emb    = (const float*)d_in[2];
    const float* ln1_g  = (const float*)d_in[3];
    const float* ln1_b  = (const float*)d_in[4];
    const float* Wqkv   = (const float*)d_in[5];
    const float* bqkv   = (const float*)d_in[6];
    const float* Wo     = (const float*)d_in[7];
    const float* bo     = (const float*)d_in[8];
    const float* ln2_g  = (const float*)d_in[9];
    const float* ln2_b  = (const float*)d_in[10];
    const float* Wfc    = (const float*)d_in[11];
    const float* bfc    = (const float*)d_in[12];
    const float* Wproj  = (const float*)d_in[13];
    const float* bproj  = (const float*)d_in[14];
    const float* lnf_g  = (const float*)d_in[15];
    const float* lnf_b  = (const float*)d_in[16];
    float* out = (float*)d_out;

    float *x, *h, *qkv, *scr, *attn, *ffn;
    cudaGetSymbolAddress((void**)&x,    g_x);
    cudaGetSymbolAddress((void**)&h,    g_h);
    cudaGetSymbolAddress((void**)&qkv,  g_qkv);
    cudaGetSymbolAddress((void**)&scr,  g_scr);
    cudaGetSymbolAddress((void**)&attn, g_attn);
    cudaGetSymbolAddress((void**)&ffn,  g_ffn);

    embed_kernel<<<Mrows, 256>>>(ids, emb, x);

    for (int l = 0; l < NLc; ++l) {
        // h = LN1(x)
        ln_kernel<<<Mrows, 256>>>(x, ln1_g + (size_t)l*Hc, ln1_b + (size_t)l*Hc, h);
        // qkv = h @ Wqkv + bqkv
        gemm_tc<false,false,false,true><<<dim3(3*Hc/128, Mrows/128), 256>>>(
            h, Wqkv + (size_t)l*Hc*3*Hc, bqkv + (size_t)l*3*Hc, qkv, Mrows, 3*Hc, Hc);
        // scores (+ alibi + masking)
        scores_kernel<<<dim3(Sc/64, Sc/64, Bc*NHc), 256>>>(qkv, sp, scr);
        // softmax
        softmax_kernel<<<Bc*NHc*Sc, 128>>>(scr);
        // attn = P @ V
        av_kernel<<<dim3(Sc/64, 1, Bc*NHc), 256>>>(scr, qkv, attn);
        // x += attn @ Wo + bo
        gemm_tc<false,true,false,true><<<dim3(Hc/128, Mrows/128), 256>>>(
            attn, Wo + (size_t)l*Hc*Hc, bo + (size_t)l*Hc, x, Mrows, Hc, Hc);
        // h = LN2(x)
        ln_kernel<<<Mrows, 256>>>(x, ln2_g + (size_t)l*Hc, ln2_b + (size_t)l*Hc, h);
        // ffn = gelu(h @ Wfc + bfc)
        gemm_tc<false,false,true,true><<<dim3(Fc/128, Mrows/128), 256>>>(
            h, Wfc + (size_t)l*Hc*Fc, bfc + (size_t)l*Fc, ffn, Mrows, Fc, Hc);
        // x += ffn @ Wproj + bproj
        gemm_tc<false,true,false,true><<<dim3(Hc/128, Mrows/128), 256>>>(
            ffn, Wproj + (size_t)l*Fc*Hc, bproj + (size_t)l*Hc, x, Mrows, Hc, Fc);
    }

    // final LN + logits = h @ emb^T
    ln_kernel<<<Mrows, 256>>>(x, lnf_g, lnf_b, h);
    gemm_tc<true,false,false,false><<<dim3(Vc/128, Mrows/128), 256>>>(
        h, emb, nullptr, out, Mrows, Vc, Hc);
}

// round 5
// speedup vs baseline: 3.4802x; 1.6455x over previous
#include <cuda_runtime.h>
#include <cuda_fp16.h>
#include <math.h>
#include <stdint.h>

// Problem constants
#define Bc   16
#define Sc   512
#define Vc   512
#define Hc   1024
#define NLc  8
#define NHc  16
#define DHc  64
#define Fc   4096
#define Mrows (Bc*Sc)   // 8192 token rows

// ---------------- scratch (static device memory; no runtime allocs) ----------------
__device__ float  g_x   [(size_t)Mrows*Hc];        // residual stream (fp32)
__device__ __half g_h   [(size_t)Mrows*Hc];        // LN output (half)
__device__ float  g_qkv [(size_t)Mrows*3*Hc];      // fused qkv (fp32)
__device__ float  g_scr [(size_t)Bc*NHc*Sc*Sc];    // attention scores / probs
__device__ __half g_attn[(size_t)Mrows*Hc];        // attention out (half)
__device__ __half g_ffn [(size_t)Mrows*Fc];        // ffn intermediate (half)
// transposed half weights per layer: [qkvT 3M | woT 1M | wfcT 4M | wprojT 4M]
#define LWT ((size_t)(3*Hc*Hc + Hc*Hc + Hc*Fc + Fc*Hc))
__device__ __half g_wT  [(size_t)NLc * LWT];
__device__ __half g_embH[(size_t)Vc*Hc];           // half emb ([V,H] == [N,K] for logits)

// ---------------- helpers ----------------
__device__ __forceinline__ float gelu_f(float x) {
    float x3 = x * x * x;
    return 0.5f * x * (1.0f + tanhf(0.7978845608028654f * (x + 0.044715f * x3)));
}
__device__ __forceinline__ void cp16(uint32_t saddr, const void* gptr) {
    asm volatile("cp.async.cg.shared.global [%0], [%1], 16;\n" :: "r"(saddr), "l"(gptr));
}
#define CP_COMMIT() asm volatile("cp.async.commit_group;\n" ::: "memory")
#define CP_WAIT1()  asm volatile("cp.async.wait_group 1;\n" ::: "memory")

__device__ __forceinline__ void ldm_x4(uint32_t r[4], uint32_t addr) {
    asm volatile("ldmatrix.sync.aligned.m8n8.x4.shared.b16 {%0,%1,%2,%3}, [%4];"
                 : "=r"(r[0]), "=r"(r[1]), "=r"(r[2]), "=r"(r[3]) : "r"(addr));
}
__device__ __forceinline__ void mma_f16(float c[4], const uint32_t a[4],
                                        uint32_t b0, uint32_t b1) {
    asm volatile(
        "mma.sync.aligned.m16n8k16.row.col.f32.f16.f16.f32 "
        "{%0,%1,%2,%3}, {%4,%5,%6,%7}, {%8,%9}, {%0,%1,%2,%3};"
        : "+f"(c[0]), "+f"(c[1]), "+f"(c[2]), "+f"(c[3])
        : "r"(a[0]), "r"(a[1]), "r"(a[2]), "r"(a[3]), "r"(b0), "r"(b1));
}

// ---------------- weight transpose to half: in [K,N] -> out [N,K] ----------------
__global__ void transpose_half(const float* __restrict__ in, __half* __restrict__ out,
                               int K, int N) {
    __shared__ float t[32][33];
    int n0 = blockIdx.x * 32, k0 = blockIdx.y * 32;
    int tx = threadIdx.x, ty = threadIdx.y;  // (32,8)
    #pragma unroll
    for (int r = 0; r < 32; r += 8)
        t[ty + r][tx] = in[(size_t)(k0 + ty + r) * N + n0 + tx];
    __syncthreads();
    #pragma unroll
    for (int r = 0; r < 32; r += 8)
        out[(size_t)(n0 + ty + r) * K + k0 + tx] = __float2half_rn(t[tx][ty + r]);
}

__global__ void half_copy(const float* __restrict__ in, __half* __restrict__ out) {
    int i = blockIdx.x * 256 + threadIdx.x;
    float4 v = ((const float4*)in)[i];
    __half2 h0 = __floats2half2_rn(v.x, v.y);
    __half2 h1 = __floats2half2_rn(v.z, v.w);
    ((__half2*)out)[2*i]   = h0;
    ((__half2*)out)[2*i+1] = h1;
}

// ---------------- embedding gather ----------------
__global__ void embed_kernel(const int* __restrict__ ids,
                             const float* __restrict__ emb,
                             float* __restrict__ out) {
    int t = blockIdx.x;
    int id = ids[t];
    const float4* src = (const float4*)(emb + (size_t)id * Hc);
    float4* dst = (float4*)(out + (size_t)t * Hc);
    dst[threadIdx.x] = src[threadIdx.x];
}

// ---------------- layernorm (half output) ----------------
__global__ void ln_kernel(const float* __restrict__ x,
                          const float* __restrict__ g,
                          const float* __restrict__ b,
                          __half* __restrict__ out) {
    __shared__ float s1[256], s2[256];
    int row = blockIdx.x, tid = threadIdx.x;
    float4 v = ((const float4*)(x + (size_t)row * Hc))[tid];
    s1[tid] = v.x + v.y + v.z + v.w;
    s2[tid] = v.x*v.x + v.y*v.y + v.z*v.z + v.w*v.w;
    __syncthreads();
    for (int s = 128; s > 0; s >>= 1) {
        if (tid < s) { s1[tid] += s1[tid+s]; s2[tid] += s2[tid+s]; }
        __syncthreads();
    }
    float mu  = s1[0] * (1.0f / Hc);
    float var = s2[0] * (1.0f / Hc) - mu * mu;
    float inv = rsqrtf(var + 1e-5f);
    float4 gg = ((const float4*)g)[tid];
    float4 bb = ((const float4*)b)[tid];
    __half2 h0 = __floats2half2_rn((v.x - mu) * inv * gg.x + bb.x,
                                   (v.y - mu) * inv * gg.y + bb.y);
    __half2 h1 = __floats2half2_rn((v.z - mu) * inv * gg.z + bb.z,
                                   (v.w - mu) * inv * gg.w + bb.w);
    __half2* op = (__half2*)(out + (size_t)row * Hc);
    op[2*tid]   = h0;
    op[2*tid+1] = h1;
}

// ---------------- fp16 tensor-core GEMM: C = act(A@Wt^T + bias) (+= residual C) ------
// A [M,K] half, Wt [N,K] half. 128x128 tile, BK=64, 3-stage cp.async, 256 threads.
// smem rows: 128 bytes (64 halves), swizzle chunk^(row&7).
template<bool RES, bool GELU_ACT, bool BIAS, bool OUT_HALF>
__global__ __launch_bounds__(256, 2)
void gemm_h(const __half* __restrict__ A, const __half* __restrict__ Wt,
            const float* __restrict__ bias, void* __restrict__ Cv,
            int N, int K) {
    extern __shared__ uint8_t dsm[];
    uint32_t smem = (uint32_t)__cvta_generic_to_shared(dsm);
    const uint32_t sA = smem;            // 3 stages x 16KB
    const uint32_t sB = smem + 49152;    // 3 stages x 16KB

    int tid = threadIdx.x, wid = tid >> 5, lane = tid & 31;
    int m0 = blockIdx.y * 128, n0 = blockIdx.x * 128;
    int warpM = (wid >> 2) * 64;
    int warpN = (wid & 3) * 32;
    int nIter = K >> 6;

    float acc[4][4][4];
    #pragma unroll
    for (int i = 0; i < 4; ++i)
        #pragma unroll
        for (int j = 0; j < 4; ++j)
            #pragma unroll
            for (int r = 0; r < 4; ++r) acc[i][j][r] = 0.f;

    // cp.async mapping: row = tid>>1 (0..127), halves offset (tid&1)*32
    int row = tid >> 1;
    int hseg = (tid & 1) * 32;
    const __half* ag = A  + (size_t)(m0 + row) * K + hseg;
    const __half* bg = Wt + (size_t)(n0 + row) * K + hseg;
    uint32_t so[4];
    #pragma unroll
    for (int i = 0; i < 4; ++i) {
        int c = (tid & 1) * 4 + i;
        so[i] = row * 128 + ((c ^ (row & 7)) << 4);
    }

    auto prefetch = [&](int it) {
        if (it < nIter) {
            uint32_t a_st = sA + (it % 3) * 16384;
            uint32_t b_st = sB + (it % 3) * 16384;
            const __half* ap = ag + (size_t)it * 64;
            const __half* bp = bg + (size_t)it * 64;
            #pragma unroll
            for (int i = 0; i < 4; ++i) cp16(a_st + so[i], ap + 8 * i);
            #pragma unroll
            for (int i = 0; i < 4; ++i) cp16(b_st + so[i], bp + 8 * i);
        }
        CP_COMMIT();
    };

    prefetch(0);
    prefetch(1);

    // ldmatrix lane addressing: row = base + (lane&15), chunk += (lane>>4)
    int lrow = lane & 15;
    int lchk = lane >> 4;

    for (int it = 0; it < nIter; ++it) {
        CP_WAIT1();
        __syncthreads();
        uint32_t aBase = sA + (it % 3) * 16384;
        uint32_t bBase = sB + (it % 3) * 16384;
        #pragma unroll
        for (int ks = 0; ks < 4; ++ks) {
            uint32_t af[4][4], bf[2][4];
            #pragma unroll
            for (int mf = 0; mf < 4; ++mf) {
                int r = warpM + mf * 16 + lrow;
                int c = ks * 2 + lchk;
                ldm_x4(af[mf], aBase + r * 128 + ((c ^ (r & 7)) << 4));
            }
            #pragma unroll
            for (int g = 0; g < 2; ++g) {
                int r = warpN + g * 16 + lrow;
                int c = ks * 2 + lchk;
                ldm_x4(bf[g], bBase + r * 128 + ((c ^ (r & 7)) << 4));
            }
            #pragma unroll
            for (int mf = 0; mf < 4; ++mf) {
                mma_f16(acc[mf][0], af[mf], bf[0][0], bf[0][2]);
                mma_f16(acc[mf][1], af[mf], bf[0][1], bf[0][3]);
                mma_f16(acc[mf][2], af[mf], bf[1][0], bf[1][2]);
                mma_f16(acc[mf][3], af[mf], bf[1][1], bf[1][3]);
            }
        }
        __syncthreads();
        prefetch(it + 2);
    }

    // epilogue
    int rbase = m0 + warpM + (lane >> 2);
    int cbase = n0 + warpN + (lane & 3) * 2;
    #pragma unroll
    for (int mf = 0; mf < 4; ++mf) {
        #pragma unroll
        for (int nf = 0; nf < 4; ++nf) {
            int c = cbase + nf * 8;
            float bx = 0.f, by = 0.f;
            if (BIAS) { bx = bias[c]; by = bias[c + 1]; }
            #pragma unroll
            for (int half_ = 0; half_ < 2; ++half_) {
                int r = rbase + mf * 16 + half_ * 8;
                float v0 = acc[mf][nf][half_ * 2 + 0] + bx;
                float v1 = acc[mf][nf][half_ * 2 + 1] + by;
                if (GELU_ACT) { v0 = gelu_f(v0); v1 = gelu_f(v1); }
                if (OUT_HALF) {
                    __half2* cp = (__half2*)((__half*)Cv + (size_t)r * N + c);
                    *cp = __floats2half2_rn(v0, v1);
                } else {
                    float2* cp = (float2*)((float*)Cv + (size_t)r * N + c);
                    if (RES) { float2 old = *cp; v0 += old.x; v1 += old.y; }
                    float2 o; o.x = v0; o.y = v1;
                    *cp = o;
                }
            }
        }
    }
}

// ---------------- attention scores: q@k^T * scale + alibi/mask ----------------
__global__ __launch_bounds__(256)
void scores_kernel(const float* __restrict__ qkv, const int* __restrict__ sp,
                   float* __restrict__ scores) {
    int bz = blockIdx.z;
    int b = bz >> 4, n = bz & 15;
    int i0 = blockIdx.y * 64, j0 = blockIdx.x * 64;
    __shared__ float Qs[16][64], Ks[16][64];
    int tid = threadIdx.x;
    int tx = tid & 15, ty = tid >> 4;
    float acc[4][4] = {};
    const float* qbase = qkv + (size_t)b * Sc * 3 * Hc + n * DHc;
    const float* kbase = qbase + Hc;
    int lr = tid >> 2;
    int lc = (tid & 3) * 4;

    for (int k0 = 0; k0 < DHc; k0 += 16) {
        float4 qv = *(const float4*)&qbase[(size_t)(i0 + lr) * 3 * Hc + k0 + lc];
        Qs[lc+0][lr] = qv.x; Qs[lc+1][lr] = qv.y; Qs[lc+2][lr] = qv.z; Qs[lc+3][lr] = qv.w;
        float4 kv = *(const float4*)&kbase[(size_t)(j0 + lr) * 3 * Hc + k0 + lc];
        Ks[lc+0][lr] = kv.x; Ks[lc+1][lr] = kv.y; Ks[lc+2][lr] = kv.z; Ks[lc+3][lr] = kv.w;
        __syncthreads();
        #pragma unroll
        for (int kk = 0; kk < 16; ++kk) {
            float ra[4], rb[4];
            *(float4*)&ra[0] = *(float4*)&Qs[kk][ty*4];
            *(float4*)&rb[0] = *(float4*)&Ks[kk][tx*4];
            #pragma unroll
            for (int i = 0; i < 4; ++i)
                #pragma unroll
                for (int j = 0; j < 4; ++j)
                    acc[i][j] += ra[i] * rb[j];
        }
        __syncthreads();
    }

    int spb = sp[b];
    float slope = exp2f(-0.5f * (float)(n + 1));
    #pragma unroll
    for (int ii = 0; ii < 4; ++ii) {
        int i = i0 + ty*4 + ii;
        #pragma unroll
        for (int jj = 0; jj < 4; ++jj) {
            int j = j0 + tx*4 + jj;
            bool allowed = (j <= i) && !((i >= spb) && (j < spb));
            float val = allowed ? (acc[ii][jj] * 0.125f - slope * (float)(i - j))
                                : -1e9f;
            scores[((size_t)bz * Sc + i) * Sc + j] = val;
        }
    }
}

// ---------------- row softmax over S=512 ----------------
__global__ void softmax_kernel(float* __restrict__ scores) {
    __shared__ float sh[128];
    size_t row = blockIdx.x;
    float* p = scores + row * (size_t)Sc;
    int tid = threadIdx.x;
    float4 v = ((float4*)p)[tid];
    float mx = fmaxf(fmaxf(v.x, v.y), fmaxf(v.z, v.w));
    sh[tid] = mx; __syncthreads();
    for (int s = 64; s > 0; s >>= 1) {
        if (tid < s) sh[tid] = fmaxf(sh[tid], sh[tid+s]);
        __syncthreads();
    }
    mx = sh[0]; __syncthreads();
    v.x = expf(v.x - mx); v.y = expf(v.y - mx);
    v.z = expf(v.z - mx); v.w = expf(v.w - mx);
    sh[tid] = v.x + v.y + v.z + v.w; __syncthreads();
    for (int s = 64; s > 0; s >>= 1) {
        if (tid < s) sh[tid] += sh[tid+s];
        __syncthreads();
    }
    float inv = 1.0f / sh[0];
    v.x *= inv; v.y *= inv; v.z *= inv; v.w *= inv;
    ((float4*)p)[tid] = v;
}

// ---------------- attention A = P @ V (half output) ----------------
__global__ __launch_bounds__(256)
void av_kernel(const float* __restrict__ scores, const float* __restrict__ qkv,
               __half* __restrict__ out) {
    int bz = blockIdx.z;
    int b = bz >> 4, n = bz & 15;
    int i0 = blockIdx.x * 64;
    __shared__ float Ps[16][64], Vs[16][64];
    int tid = threadIdx.x;
    int tx = tid & 15, ty = tid >> 4;
    float acc[4][4] = {};
    const float* prow  = scores + ((size_t)bz * Sc + i0) * Sc;
    const float* vbase = qkv + (size_t)b * Sc * 3 * Hc + 2 * Hc + n * DHc;
    int lr = tid >> 2, lc = (tid & 3) * 4;
    int vr = tid >> 4, vc = (tid & 15) * 4;

    for (int j0 = 0; j0 < Sc; j0 += 16) {
        float4 pv = *(const float4*)&prow[(size_t)lr * Sc + j0 + lc];
        Ps[lc+0][lr] = pv.x; Ps[lc+1][lr] = pv.y; Ps[lc+2][lr] = pv.z; Ps[lc+3][lr] = pv.w;
        float4 vv = *(const float4*)&vbase[(size_t)(j0 + vr) * 3 * Hc + vc];
        *(float4*)&Vs[vr][vc] = vv;
        __syncthreads();
        #pragma unroll
        for (int kk = 0; kk < 16; ++kk) {
            float ra[4], rb[4];
            *(float4*)&ra[0] = *(float4*)&Ps[kk][ty*4];
            *(float4*)&rb[0] = *(float4*)&Vs[kk][tx*4];
            #pragma unroll
            for (int i = 0; i < 4; ++i)
                #pragma unroll
                for (int j = 0; j < 4; ++j)
                    acc[i][j] += ra[i] * rb[j];
        }
        __syncthreads();
    }

    #pragma unroll
    for (int ii = 0; ii < 4; ++ii) {
        int i = i0 + ty*4 + ii;
        #pragma unroll
        for (int jj = 0; jj < 2; ++jj) {
            int d = tx*4 + jj*2;
            __half2* op = (__half2*)&out[(size_t)(b * Sc + i) * Hc + n * DHc + d];
            *op = __floats2half2_rn(acc[ii][jj*2], acc[ii][jj*2+1]);
        }
    }
}

// ---------------- launch ----------------
#define GEMM_SMEM 98304

extern "C" void kernel_launch(void* const* d_in, const int* in_sizes, int n_in,
                              void* d_out, int out_size) {
    const int*   ids    = (const int*)d_in[0];
    const int*   sp     = (const int*)d_in[1];
    const float* emb    = (const float*)d_in[2];
    const float* ln1_g  = (const float*)d_in[3];
    const float* ln1_b  = (const float*)d_in[4];
    const float* Wqkv   = (const float*)d_in[5];
    const float* bqkv   = (const float*)d_in[6];
    const float* Wo     = (const float*)d_in[7];
    const float* bo     = (const float*)d_in[8];
    const float* ln2_g  = (const float*)d_in[9];
    const float* ln2_b  = (const float*)d_in[10];
    const float* Wfc    = (const float*)d_in[11];
    const float* bfc    = (const float*)d_in[12];
    const float* Wproj  = (const float*)d_in[13];
    const float* bproj  = (const float*)d_in[14];
    const float* lnf_g  = (const float*)d_in[15];
    const float* lnf_b  = (const float*)d_in[16];
    float* out = (float*)d_out;

    float *x, *qkv, *scr;
    __half *h, *attn, *ffn, *wT, *embH;
    cudaGetSymbolAddress((void**)&x,    g_x);
    cudaGetSymbolAddress((void**)&h,    g_h);
    cudaGetSymbolAddress((void**)&qkv,  g_qkv);
    cudaGetSymbolAddress((void**)&scr,  g_scr);
    cudaGetSymbolAddress((void**)&attn, g_attn);
    cudaGetSymbolAddress((void**)&ffn,  g_ffn);
    cudaGetSymbolAddress((void**)&wT,   g_wT);
    cudaGetSymbolAddress((void**)&embH, g_embH);

    cudaFuncSetAttribute(gemm_h<false,false,true,false>,
                         cudaFuncAttributeMaxDynamicSharedMemorySize, GEMM_SMEM);
    cudaFuncSetAttribute(gemm_h<true,false,true,false>,
                         cudaFuncAttributeMaxDynamicSharedMemorySize, GEMM_SMEM);
    cudaFuncSetAttribute(gemm_h<false,true,true,true>,
                         cudaFuncAttributeMaxDynamicSharedMemorySize, GEMM_SMEM);
    cudaFuncSetAttribute(gemm_h<false,false,false,false>,
                         cudaFuncAttributeMaxDynamicSharedMemorySize, GEMM_SMEM);

    const size_t oQKV = 0;
    const size_t oWO  = (size_t)3*Hc*Hc;
    const size_t oFC  = oWO + (size_t)Hc*Hc;
    const size_t oPRJ = oFC + (size_t)Hc*Fc;

    dim3 tb(32, 8);
    for (int l = 0; l < NLc; ++l) {
        __half* base = wT + (size_t)l * LWT;
        transpose_half<<<dim3(3*Hc/32, Hc/32), tb>>>(Wqkv  + (size_t)l*Hc*3*Hc, base + oQKV, Hc, 3*Hc);
        transpose_half<<<dim3(Hc/32,   Hc/32), tb>>>(Wo    + (size_t)l*Hc*Hc,   base + oWO,  Hc, Hc);
        transpose_half<<<dim3(Fc/32,   Hc/32), tb>>>(Wfc   + (size_t)l*Hc*Fc,   base + oFC,  Hc, Fc);
        transpose_half<<<dim3(Hc/32,   Fc/32), tb>>>(Wproj + (size_t)l*Fc*Hc,   base + oPRJ, Fc, Hc);
    }
    half_copy<<<(Vc*Hc/4)/256, 256>>>(emb, embH);

    embed_kernel<<<Mrows, 256>>>(ids, emb, x);

    for (int l = 0; l < NLc; ++l) {
        __half* base = wT + (size_t)l * LWT;
        ln_kernel<<<Mrows, 256>>>(x, ln1_g + (size_t)l*Hc, ln1_b + (size_t)l*Hc, h);
        gemm_h<false,false,true,false><<<dim3(3*Hc/128, Mrows/128), 256, GEMM_SMEM>>>(
            h, base + oQKV, bqkv + (size_t)l*3*Hc, qkv, 3*Hc, Hc);
        scores_kernel<<<dim3(Sc/64, Sc/64, Bc*NHc), 256>>>(qkv, sp, scr);
        softmax_kernel<<<Bc*NHc*Sc, 128>>>(scr);
        av_kernel<<<dim3(Sc/64, 1, Bc*NHc), 256>>>(scr, qkv, attn);
        gemm_h<true,false,true,false><<<dim3(Hc/128, Mrows/128), 256, GEMM_SMEM>>>(
            attn, base + oWO, bo + (size_t)l*Hc, x, Hc, Hc);
        ln_kernel<<<Mrows, 256>>>(x, ln2_g + (size_t)l*Hc, ln2_b + (size_t)l*Hc, h);
        gemm_h<false,true,true,true><<<dim3(Fc/128, Mrows/128), 256, GEMM_SMEM>>>(
            h, base + oFC, bfc + (size_t)l*Fc, ffn, Fc, Hc);
        gemm_h<true,false,true,false><<<dim3(Hc/128, Mrows/128), 256, GEMM_SMEM>>>(
            ffn, base + oPRJ, bproj + (size_t)l*Hc, x, Hc, Fc);
    }

    ln_kernel<<<Mrows, 256>>>(x, lnf_g, lnf_b, h);
    gemm_h<false,false,false,false><<<dim3(Vc/128, Mrows/128), 256, GEMM_SMEM>>>(
        h, embH, nullptr, out, Vc, Hc);
}

// round 6
// speedup vs baseline: 5.5436x; 1.5929x over previous
#include <cuda_runtime.h>
#include <cuda_fp16.h>
#include <math.h>
#include <stdint.h>

// Problem constants
#define Bc   16
#define Sc   512
#define Vc   512
#define Hc   1024
#define NLc  8
#define NHc  16
#define DHc  64
#define Fc   4096
#define Mrows (Bc*Sc)   // 8192 token rows

// ---------------- scratch (static device memory; no runtime allocs) ----------------
__device__ float  g_x   [(size_t)Mrows*Hc];        // residual stream (fp32)
__device__ __half g_h   [(size_t)Mrows*Hc];        // LN output (half)
__device__ __half g_qkvh[(size_t)Mrows*3*Hc];      // fused qkv (half)
__device__ __half g_attn[(size_t)Mrows*Hc];        // attention out (half)
__device__ __half g_ffn [(size_t)Mrows*Fc];        // ffn intermediate (half)
// transposed half weights per layer: [qkvT 3M | woT 1M | wfcT 4M | wprojT 4M]
#define LWT ((size_t)(3*Hc*Hc + Hc*Hc + Hc*Fc + Fc*Hc))
__device__ __half g_wT  [(size_t)NLc * LWT];
__device__ __half g_embH[(size_t)Vc*Hc];           // half emb ([V,H] == [N,K] for logits)

// ---------------- helpers ----------------
__device__ __forceinline__ float gelu_f(float x) {
    float x3 = x * x * x;
    return 0.5f * x * (1.0f + tanhf(0.7978845608028654f * (x + 0.044715f * x3)));
}
__device__ __forceinline__ void cp16(uint32_t saddr, const void* gptr) {
    asm volatile("cp.async.cg.shared.global [%0], [%1], 16;\n" :: "r"(saddr), "l"(gptr));
}
#define CP_COMMIT() asm volatile("cp.async.commit_group;\n" ::: "memory")
#define CP_WAIT1()  asm volatile("cp.async.wait_group 1;\n" ::: "memory")
#define CP_WAIT0()  asm volatile("cp.async.wait_group 0;\n" ::: "memory")

__device__ __forceinline__ void ldm_x4(uint32_t r[4], uint32_t addr) {
    asm volatile("ldmatrix.sync.aligned.m8n8.x4.shared.b16 {%0,%1,%2,%3}, [%4];"
                 : "=r"(r[0]), "=r"(r[1]), "=r"(r[2]), "=r"(r[3]) : "r"(addr));
}
__device__ __forceinline__ void ldm_x4_t(uint32_t r[4], uint32_t addr) {
    asm volatile("ldmatrix.sync.aligned.m8n8.x4.trans.shared.b16 {%0,%1,%2,%3}, [%4];"
                 : "=r"(r[0]), "=r"(r[1]), "=r"(r[2]), "=r"(r[3]) : "r"(addr));
}
__device__ __forceinline__ void mma_f16(float c[4], const uint32_t a[4],
                                        uint32_t b0, uint32_t b1) {
    asm volatile(
        "mma.sync.aligned.m16n8k16.row.col.f32.f16.f16.f32 "
        "{%0,%1,%2,%3}, {%4,%5,%6,%7}, {%8,%9}, {%0,%1,%2,%3};"
        : "+f"(c[0]), "+f"(c[1]), "+f"(c[2]), "+f"(c[3])
        : "r"(a[0]), "r"(a[1]), "r"(a[2]), "r"(a[3]), "r"(b0), "r"(b1));
}
__device__ __forceinline__ uint32_t pack_h2(float a, float b) {
    __half2 h = __floats2half2_rn(a, b);
    return *(uint32_t*)&h;
}

// ---------------- weight transpose to half: in [K,N] -> out [N,K] ----------------
__global__ void transpose_half(const float* __restrict__ in, __half* __restrict__ out,
                               int K, int N) {
    __shared__ float t[32][33];
    int n0 = blockIdx.x * 32, k0 = blockIdx.y * 32;
    int tx = threadIdx.x, ty = threadIdx.y;  // (32,8)
    #pragma unroll
    for (int r = 0; r < 32; r += 8)
        t[ty + r][tx] = in[(size_t)(k0 + ty + r) * N + n0 + tx];
    __syncthreads();
    #pragma unroll
    for (int r = 0; r < 32; r += 8)
        out[(size_t)(n0 + ty + r) * K + k0 + tx] = __float2half_rn(t[tx][ty + r]);
}

__global__ void half_copy(const float* __restrict__ in, __half* __restrict__ out) {
    int i = blockIdx.x * 256 + threadIdx.x;
    float4 v = ((const float4*)in)[i];
    ((__half2*)out)[2*i]   = __floats2half2_rn(v.x, v.y);
    ((__half2*)out)[2*i+1] = __floats2half2_rn(v.z, v.w);
}

// ---------------- embedding gather ----------------
__global__ void embed_kernel(const int* __restrict__ ids,
                             const float* __restrict__ emb,
                             float* __restrict__ out) {
    int t = blockIdx.x;
    int id = ids[t];
    const float4* src = (const float4*)(emb + (size_t)id * Hc);
    float4* dst = (float4*)(out + (size_t)t * Hc);
    dst[threadIdx.x] = src[threadIdx.x];
}

// ---------------- layernorm (half output) ----------------
__global__ void ln_kernel(const float* __restrict__ x,
                          const float* __restrict__ g,
                          const float* __restrict__ b,
                          __half* __restrict__ out) {
    __shared__ float s1[256], s2[256];
    int row = blockIdx.x, tid = threadIdx.x;
    float4 v = ((const float4*)(x + (size_t)row * Hc))[tid];
    s1[tid] = v.x + v.y + v.z + v.w;
    s2[tid] = v.x*v.x + v.y*v.y + v.z*v.z + v.w*v.w;
    __syncthreads();
    for (int s = 128; s > 0; s >>= 1) {
        if (tid < s) { s1[tid] += s1[tid+s]; s2[tid] += s2[tid+s]; }
        __syncthreads();
    }
    float mu  = s1[0] * (1.0f / Hc);
    float var = s2[0] * (1.0f / Hc) - mu * mu;
    float inv = rsqrtf(var + 1e-5f);
    float4 gg = ((const float4*)g)[tid];
    float4 bb = ((const float4*)b)[tid];
    __half2* op = (__half2*)(out + (size_t)row * Hc);
    op[2*tid]   = __floats2half2_rn((v.x - mu) * inv * gg.x + bb.x,
                                    (v.y - mu) * inv * gg.y + bb.y);
    op[2*tid+1] = __floats2half2_rn((v.z - mu) * inv * gg.z + bb.z,
                                    (v.w - mu) * inv * gg.w + bb.w);
}

// ---------------- fp16 tensor-core GEMM: C = act(A@Wt^T + bias) (+= residual C) ------
template<bool RES, bool GELU_ACT, bool BIAS, bool OUT_HALF>
__global__ __launch_bounds__(256, 2)
void gemm_h(const __half* __restrict__ A, const __half* __restrict__ Wt,
            const float* __restrict__ bias, void* __restrict__ Cv,
            int N, int K) {
    extern __shared__ uint8_t dsm[];
    uint32_t smem = (uint32_t)__cvta_generic_to_shared(dsm);
    const uint32_t sA = smem;            // 3 stages x 16KB
    const uint32_t sB = smem + 49152;    // 3 stages x 16KB

    int tid = threadIdx.x, wid = tid >> 5, lane = tid & 31;
    int m0 = blockIdx.y * 128, n0 = blockIdx.x * 128;
    int warpM = (wid >> 2) * 64;
    int warpN = (wid & 3) * 32;
    int nIter = K >> 6;

    float acc[4][4][4];
    #pragma unroll
    for (int i = 0; i < 4; ++i)
        #pragma unroll
        for (int j = 0; j < 4; ++j)
            #pragma unroll
            for (int r = 0; r < 4; ++r) acc[i][j][r] = 0.f;

    int row = tid >> 1;
    int hseg = (tid & 1) * 32;
    const __half* ag = A  + (size_t)(m0 + row) * K + hseg;
    const __half* bg = Wt + (size_t)(n0 + row) * K + hseg;
    uint32_t so[4];
    #pragma unroll
    for (int i = 0; i < 4; ++i) {
        int c = (tid & 1) * 4 + i;
        so[i] = row * 128 + ((c ^ (row & 7)) << 4);
    }

    auto prefetch = [&](int it) {
        if (it < nIter) {
            uint32_t a_st = sA + (it % 3) * 16384;
            uint32_t b_st = sB + (it % 3) * 16384;
            const __half* ap = ag + (size_t)it * 64;
            const __half* bp = bg + (size_t)it * 64;
            #pragma unroll
            for (int i = 0; i < 4; ++i) cp16(a_st + so[i], ap + 8 * i);
            #pragma unroll
            for (int i = 0; i < 4; ++i) cp16(b_st + so[i], bp + 8 * i);
        }
        CP_COMMIT();
    };

    prefetch(0);
    prefetch(1);

    int lrow = lane & 15;
    int lchk = lane >> 4;

    for (int it = 0; it < nIter; ++it) {
        CP_WAIT1();
        __syncthreads();
        uint32_t aBase = sA + (it % 3) * 16384;
        uint32_t bBase = sB + (it % 3) * 16384;
        #pragma unroll
        for (int ks = 0; ks < 4; ++ks) {
            uint32_t af[4][4], bf[2][4];
            #pragma unroll
            for (int mf = 0; mf < 4; ++mf) {
                int r = warpM + mf * 16 + lrow;
                int c = ks * 2 + lchk;
                ldm_x4(af[mf], aBase + r * 128 + ((c ^ (r & 7)) << 4));
            }
            #pragma unroll
            for (int g = 0; g < 2; ++g) {
                int r = warpN + g * 16 + lrow;
                int c = ks * 2 + lchk;
                ldm_x4(bf[g], bBase + r * 128 + ((c ^ (r & 7)) << 4));
            }
            #pragma unroll
            for (int mf = 0; mf < 4; ++mf) {
                mma_f16(acc[mf][0], af[mf], bf[0][0], bf[0][2]);
                mma_f16(acc[mf][1], af[mf], bf[0][1], bf[0][3]);
                mma_f16(acc[mf][2], af[mf], bf[1][0], bf[1][2]);
                mma_f16(acc[mf][3], af[mf], bf[1][1], bf[1][3]);
            }
        }
        __syncthreads();
        prefetch(it + 2);
    }

    int rbase = m0 + warpM + (lane >> 2);
    int cbase = n0 + warpN + (lane & 3) * 2;
    #pragma unroll
    for (int mf = 0; mf < 4; ++mf) {
        #pragma unroll
        for (int nf = 0; nf < 4; ++nf) {
            int c = cbase + nf * 8;
            float bx = 0.f, by = 0.f;
            if (BIAS) { bx = bias[c]; by = bias[c + 1]; }
            #pragma unroll
            for (int half_ = 0; half_ < 2; ++half_) {
                int r = rbase + mf * 16 + half_ * 8;
                float v0 = acc[mf][nf][half_ * 2 + 0] + bx;
                float v1 = acc[mf][nf][half_ * 2 + 1] + by;
                if (GELU_ACT) { v0 = gelu_f(v0); v1 = gelu_f(v1); }
                if (OUT_HALF) {
                    __half2* cp = (__half2*)((__half*)Cv + (size_t)r * N + c);
                    *cp = __floats2half2_rn(v0, v1);
                } else {
                    float2* cp = (float2*)((float*)Cv + (size_t)r * N + c);
                    if (RES) { float2 old = *cp; v0 += old.x; v1 += old.y; }
                    float2 o; o.x = v0; o.y = v1;
                    *cp = o;
                }
            }
        }
    }
}

// ---------------- fused flash attention ----------------
// grid: (S/128, B*NH); 256 threads (8 warps x 16 rows). K/V 64-row tiles, double buffered.
__global__ __launch_bounds__(256)
void flash_kernel(const __half* __restrict__ qkvh, const int* __restrict__ sp,
                  __half* __restrict__ out) {
    __shared__ __align__(128) uint8_t sm[49152];
    uint32_t S0 = (uint32_t)__cvta_generic_to_shared(sm);
    const uint32_t sQ = S0;
    int tid = threadIdx.x, w = tid >> 5, lane = tid & 31;
    int i0 = blockIdx.x * 128;
    int bz = blockIdx.y;
    int b = bz >> 4, n = bz & 15;
    int spb = sp[b];
    float slope = exp2f(-0.5f * (float)(n + 1));

    const __half* qbase = qkvh + (size_t)b * Sc * 3 * Hc + n * 64;

    // Q tile 128x64 -> smem
    #pragma unroll
    for (int itr = 0; itr < 4; ++itr) {
        int id = itr * 256 + tid;
        int row = id >> 3, ch = id & 7;
        cp16(sQ + row * 128 + ((ch ^ (row & 7)) << 4),
             qbase + (size_t)(i0 + row) * 3 * Hc + ch * 8);
    }
    auto prefKV = [&](int jt) {
        int stage = jt & 1;
        uint32_t sK = S0 + 16384 + stage * 16384;
        uint32_t sV = sK + 8192;
        int j0 = jt * 64;
        #pragma unroll
        for (int itr = 0; itr < 2; ++itr) {
            int id = itr * 256 + tid;
            int row = id >> 3, ch = id & 7;
            uint32_t sw = row * 128 + ((ch ^ (row & 7)) << 4);
            const __half* g = qbase + (size_t)(j0 + row) * 3 * Hc + ch * 8;
            cp16(sK + sw, g + Hc);
            cp16(sV + sw, g + 2 * Hc);
        }
    };
    prefKV(0);
    CP_COMMIT();

    int jtmax = blockIdx.x * 2 + 1;
    int ibase = i0 + w * 16;
    int irow = ibase + (lane >> 2);
    int jcl = (lane & 3) * 2;

    float m_run[2] = {-1e30f, -1e30f};
    float l[2] = {0.f, 0.f};
    float co[8][4];
    #pragma unroll
    for (int i = 0; i < 8; ++i)
        #pragma unroll
        for (int j = 0; j < 4; ++j) co[i][j] = 0.f;
    uint32_t aq[4][4];
    bool qLoaded = false;

    for (int jt = 0; jt <= jtmax; ++jt) {
        bool hasNext = jt < jtmax;
        if (hasNext) { prefKV(jt + 1); CP_COMMIT(); }
        if (hasNext) { CP_WAIT1(); } else { CP_WAIT0(); }
        __syncthreads();
        int stage = jt & 1;
        uint32_t sK = S0 + 16384 + stage * 16384;
        uint32_t sV = sK + 8192;
        if (!qLoaded) {
            qLoaded = true;
            #pragma unroll
            for (int kc = 0; kc < 4; ++kc) {
                int r = w * 16 + (lane & 15);
                int c = kc * 2 + (lane >> 4);
                ldm_x4(aq[kc], sQ + r * 128 + ((c ^ (r & 7)) << 4));
            }
        }
        int j0 = jt * 64;
        if (j0 <= ibase + 15) {
            float c[8][4];
            #pragma unroll
            for (int i = 0; i < 8; ++i)
                #pragma unroll
                for (int j = 0; j < 4; ++j) c[i][j] = 0.f;
            // S = Q K^T
            #pragma unroll
            for (int kc = 0; kc < 4; ++kc) {
                uint32_t bf[4][4];
                #pragma unroll
                for (int g = 0; g < 4; ++g) {
                    int r = g * 16 + (lane & 15);
                    int cc = kc * 2 + (lane >> 4);
                    ldm_x4(bf[g], sK + r * 128 + ((cc ^ (r & 7)) << 4));
                }
                #pragma unroll
                for (int g = 0; g < 4; ++g) {
                    mma_f16(c[g * 2],     aq[kc], bf[g][0], bf[g][2]);
                    mma_f16(c[g * 2 + 1], aq[kc], bf[g][1], bf[g][3]);
                }
            }
            // mask + alibi
            float tmax[2] = {-1e30f, -1e30f};
            #pragma unroll
            for (int nf = 0; nf < 8; ++nf)
                #pragma unroll
                for (int rg = 0; rg < 4; ++rg) {
                    int i = irow + (rg >> 1) * 8;
                    int j = j0 + nf * 8 + jcl + (rg & 1);
                    bool ok = (j <= i) && !((i >= spb) && (j < spb));
                    float v = ok ? fmaf(c[nf][rg], 0.125f, -slope * (float)(i - j))
                                 : -1e9f;
                    c[nf][rg] = v;
                    tmax[rg >> 1] = fmaxf(tmax[rg >> 1], v);
                }
            float sfv[2];
            #pragma unroll
            for (int h = 0; h < 2; ++h) {
                tmax[h] = fmaxf(tmax[h], __shfl_xor_sync(0xffffffffu, tmax[h], 1));
                tmax[h] = fmaxf(tmax[h], __shfl_xor_sync(0xffffffffu, tmax[h], 2));
                float mn = fmaxf(m_run[h], tmax[h]);
                sfv[h] = __expf(m_run[h] - mn);
                m_run[h] = mn;
            }
            float rs[2] = {0.f, 0.f};
            #pragma unroll
            for (int nf = 0; nf < 8; ++nf)
                #pragma unroll
                for (int rg = 0; rg < 4; ++rg) {
                    float p = __expf(c[nf][rg] - m_run[rg >> 1]);
                    c[nf][rg] = p;
                    rs[rg >> 1] += p;
                }
            #pragma unroll
            for (int h = 0; h < 2; ++h) {
                rs[h] += __shfl_xor_sync(0xffffffffu, rs[h], 1);
                rs[h] += __shfl_xor_sync(0xffffffffu, rs[h], 2);
                l[h] = l[h] * sfv[h] + rs[h];
            }
            #pragma unroll
            for (int nf = 0; nf < 8; ++nf)
                #pragma unroll
                for (int rg = 0; rg < 4; ++rg) co[nf][rg] *= sfv[rg >> 1];
            // P fragments (register reshuffle)
            uint32_t ap[4][4];
            #pragma unroll
            for (int kc = 0; kc < 4; ++kc) {
                ap[kc][0] = pack_h2(c[2*kc][0],   c[2*kc][1]);
                ap[kc][1] = pack_h2(c[2*kc][2],   c[2*kc][3]);
                ap[kc][2] = pack_h2(c[2*kc+1][0], c[2*kc+1][1]);
                ap[kc][3] = pack_h2(c[2*kc+1][2], c[2*kc+1][3]);
            }
            // O += P V
            #pragma unroll
            for (int kc = 0; kc < 4; ++kc) {
                #pragma unroll
                for (int dp = 0; dp < 4; ++dp) {
                    uint32_t vf[4];
                    int r = kc * 16 + (lane & 15);
                    int cc = dp * 2 + (lane >> 4);
                    ldm_x4_t(vf, sV + r * 128 + ((cc ^ (r & 7)) << 4));
                    mma_f16(co[dp * 2],     ap[kc], vf[0], vf[1]);
                    mma_f16(co[dp * 2 + 1], ap[kc], vf[2], vf[3]);
                }
            }
        }
        __syncthreads();
    }

    float inv0 = 1.0f / l[0], inv1 = 1.0f / l[1];
    #pragma unroll
    for (int nf = 0; nf < 8; ++nf) {
        int cidx = n * 64 + nf * 8 + jcl;
        __half2* o0 = (__half2*)&out[(size_t)(b * Sc + irow) * Hc + cidx];
        *o0 = __floats2half2_rn(co[nf][0] * inv0, co[nf][1] * inv0);
        __half2* o1 = (__half2*)&out[(size_t)(b * Sc + irow + 8) * Hc + cidx];
        *o1 = __floats2half2_rn(co[nf][2] * inv1, co[nf][3] * inv1);
    }
}

// ---------------- launch ----------------
#define GEMM_SMEM 98304

extern "C" void kernel_launch(void* const* d_in, const int* in_sizes, int n_in,
                              void* d_out, int out_size) {
    const int*   ids    = (const int*)d_in[0];
    const int*   sp     = (const int*)d_in[1];
    const float* emb    = (const float*)d_in[2];
    const float* ln1_g  = (const float*)d_in[3];
    const float* ln1_b  = (const float*)d_in[4];
    const float* Wqkv   = (const float*)d_in[5];
    const float* bqkv   = (const float*)d_in[6];
    const float* Wo     = (const float*)d_in[7];
    const float* bo     = (const float*)d_in[8];
    const float* ln2_g  = (const float*)d_in[9];
    const float* ln2_b  = (const float*)d_in[10];
    const float* Wfc    = (const float*)d_in[11];
    const float* bfc    = (const float*)d_in[12];
    const float* Wproj  = (const float*)d_in[13];
    const float* bproj  = (const float*)d_in[14];
    const float* lnf_g  = (const float*)d_in[15];
    const float* lnf_b  = (const float*)d_in[16];
    float* out = (float*)d_out;

    float *x;
    __half *h, *qkvh, *attn, *ffn, *wT, *embH;
    cudaGetSymbolAddress((void**)&x,    g_x);
    cudaGetSymbolAddress((void**)&h,    g_h);
    cudaGetSymbolAddress((void**)&qkvh, g_qkvh);
    cudaGetSymbolAddress((void**)&attn, g_attn);
    cudaGetSymbolAddress((void**)&ffn,  g_ffn);
    cudaGetSymbolAddress((void**)&wT,   g_wT);
    cudaGetSymbolAddress((void**)&embH, g_embH);

    cudaFuncSetAttribute(gemm_h<false,false,true,true>,
                         cudaFuncAttributeMaxDynamicSharedMemorySize, GEMM_SMEM);
    cudaFuncSetAttribute(gemm_h<true,false,true,false>,
                         cudaFuncAttributeMaxDynamicSharedMemorySize, GEMM_SMEM);
    cudaFuncSetAttribute(gemm_h<false,true,true,true>,
                         cudaFuncAttributeMaxDynamicSharedMemorySize, GEMM_SMEM);
    cudaFuncSetAttribute(gemm_h<false,false,false,false>,
                         cudaFuncAttributeMaxDynamicSharedMemorySize, GEMM_SMEM);

    const size_t oQKV = 0;
    const size_t oWO  = (size_t)3*Hc*Hc;
    const size_t oFC  = oWO + (size_t)Hc*Hc;
    const size_t oPRJ = oFC + (size_t)Hc*Fc;

    dim3 tb(32, 8);
    for (int l = 0; l < NLc; ++l) {
        __half* base = wT + (size_t)l * LWT;
        transpose_half<<<dim3(3*Hc/32, Hc/32), tb>>>(Wqkv  + (size_t)l*Hc*3*Hc, base + oQKV, Hc, 3*Hc);
        transpose_half<<<dim3(Hc/32,   Hc/32), tb>>>(Wo    + (size_t)l*Hc*Hc,   base + oWO,  Hc, Hc);
        transpose_half<<<dim3(Fc/32,   Hc/32), tb>>>(Wfc   + (size_t)l*Hc*Fc,   base + oFC,  Hc, Fc);
        transpose_half<<<dim3(Hc/32,   Fc/32), tb>>>(Wproj + (size_t)l*Fc*Hc,   base + oPRJ, Fc, Hc);
    }
    half_copy<<<(Vc*Hc/4)/256, 256>>>(emb, embH);

    embed_kernel<<<Mrows, 256>>>(ids, emb, x);

    for (int l = 0; l < NLc; ++l) {
        __half* base = wT + (size_t)l * LWT;
        ln_kernel<<<Mrows, 256>>>(x, ln1_g + (size_t)l*Hc, ln1_b + (size_t)l*Hc, h);
        gemm_h<false,false,true,true><<<dim3(3*Hc/128, Mrows/128), 256, GEMM_SMEM>>>(
            h, base + oQKV, bqkv + (size_t)l*3*Hc, qkvh, 3*Hc, Hc);
        flash_kernel<<<dim3(Sc/128, Bc*NHc), 256>>>(qkvh, sp, attn);
        gemm_h<true,false,true,false><<<dim3(Hc/128, Mrows/128), 256, GEMM_SMEM>>>(
            attn, base + oWO, bo + (size_t)l*Hc, x, Hc, Hc);
        ln_kernel<<<Mrows, 256>>>(x, ln2_g + (size_t)l*Hc, ln2_b + (size_t)l*Hc, h);
        gemm_h<false,true,true,true><<<dim3(Fc/128, Mrows/128), 256, GEMM_SMEM>>>(
            h, base + oFC, bfc + (size_t)l*Fc, ffn, Fc, Hc);
        gemm_h<true,false,true,false><<<dim3(Hc/128, Mrows/128), 256, GEMM_SMEM>>>(
            ffn, base + oPRJ, bproj + (size_t)l*Hc, x, Hc, Fc);
    }

    ln_kernel<<<Mrows, 256>>>(x, lnf_g, lnf_b, h);
    gemm_h<false,false,false,false><<<dim3(Vc/128, Mrows/128), 256, GEMM_SMEM>>>(
        h, embH, nullptr, out, Vc, Hc);
}

// round 7
// speedup vs baseline: 5.7591x; 1.0389x over previous
#include <cuda_runtime.h>
#include <cuda_fp16.h>
#include <math.h>
#include <stdint.h>

// Problem constants
#define Bc   16
#define Sc   512
#define Vc   512
#define Hc   1024
#define NLc  8
#define NHc  16
#define DHc  64
#define Fc   4096
#define Mrows (Bc*Sc)   // 8192 token rows

// ---------------- scratch (static device memory; no runtime allocs) ----------------
__device__ float  g_x   [(size_t)Mrows*Hc];        // residual stream (fp32)
__device__ __half g_h   [(size_t)Mrows*Hc];        // LN output (half)
__device__ __half g_qkvh[(size_t)Mrows*3*Hc];      // fused qkv (half)
__device__ __half g_attn[(size_t)Mrows*Hc];        // attention out (half)
__device__ __half g_ffn [(size_t)Mrows*Fc];        // ffn intermediate (half)
// transposed half weights per layer: [qkvT 3M | woT 1M | wfcT 4M | wprojT 4M]
#define LWT ((size_t)(3*Hc*Hc + Hc*Hc + Hc*Fc + Fc*Hc))
__device__ __half g_wT  [(size_t)NLc * LWT];
__device__ __half g_embH[(size_t)Vc*Hc];           // half emb ([V,H] == [N,K] for logits)

// ---------------- helpers ----------------
__device__ __forceinline__ float gelu_f(float x) {
    // tanh-approx gelu, with tanh(u) = 1 - 2/(e^{2u}+1) via fast exp (err ~1e-7)
    float u = 0.7978845608028654f * (x + 0.044715f * x * x * x);
    float t = 1.0f - 2.0f / (__expf(2.0f * u) + 1.0f);
    return 0.5f * x * (1.0f + t);
}
__device__ __forceinline__ void cp16(uint32_t saddr, const void* gptr) {
    asm volatile("cp.async.cg.shared.global [%0], [%1], 16;\n" :: "r"(saddr), "l"(gptr));
}
#define CP_COMMIT() asm volatile("cp.async.commit_group;\n" ::: "memory")
#define CP_WAIT1()  asm volatile("cp.async.wait_group 1;\n" ::: "memory")
#define CP_WAIT0()  asm volatile("cp.async.wait_group 0;\n" ::: "memory")

__device__ __forceinline__ void ldm_x4(uint32_t r[4], uint32_t addr) {
    asm volatile("ldmatrix.sync.aligned.m8n8.x4.shared.b16 {%0,%1,%2,%3}, [%4];"
                 : "=r"(r[0]), "=r"(r[1]), "=r"(r[2]), "=r"(r[3]) : "r"(addr));
}
__device__ __forceinline__ void ldm_x4_t(uint32_t r[4], uint32_t addr) {
    asm volatile("ldmatrix.sync.aligned.m8n8.x4.trans.shared.b16 {%0,%1,%2,%3}, [%4];"
                 : "=r"(r[0]), "=r"(r[1]), "=r"(r[2]), "=r"(r[3]) : "r"(addr));
}
__device__ __forceinline__ void mma_f16(float c[4], const uint32_t a[4],
                                        uint32_t b0, uint32_t b1) {
    asm volatile(
        "mma.sync.aligned.m16n8k16.row.col.f32.f16.f16.f32 "
        "{%0,%1,%2,%3}, {%4,%5,%6,%7}, {%8,%9}, {%0,%1,%2,%3};"
        : "+f"(c[0]), "+f"(c[1]), "+f"(c[2]), "+f"(c[3])
        : "r"(a[0]), "r"(a[1]), "r"(a[2]), "r"(a[3]), "r"(b0), "r"(b1));
}
__device__ __forceinline__ uint32_t pack_h2(float a, float b) {
    __half2 h = __floats2half2_rn(a, b);
    return *(uint32_t*)&h;
}

// ---------------- weight transpose to half: in [K,N] -> out [N,K] ----------------
__global__ void transpose_half(const float* __restrict__ in, __half* __restrict__ out,
                               int K, int N) {
    __shared__ float t[32][33];
    int n0 = blockIdx.x * 32, k0 = blockIdx.y * 32;
    int tx = threadIdx.x, ty = threadIdx.y;  // (32,8)
    #pragma unroll
    for (int r = 0; r < 32; r += 8)
        t[ty + r][tx] = in[(size_t)(k0 + ty + r) * N + n0 + tx];
    __syncthreads();
    #pragma unroll
    for (int r = 0; r < 32; r += 8)
        out[(size_t)(n0 + ty + r) * K + k0 + tx] = __float2half_rn(t[tx][ty + r]);
}

__global__ void half_copy(const float* __restrict__ in, __half* __restrict__ out) {
    int i = blockIdx.x * 256 + threadIdx.x;
    float4 v = ((const float4*)in)[i];
    ((__half2*)out)[2*i]   = __floats2half2_rn(v.x, v.y);
    ((__half2*)out)[2*i+1] = __floats2half2_rn(v.z, v.w);
}

// ---------------- embedding gather ----------------
__global__ void embed_kernel(const int* __restrict__ ids,
                             const float* __restrict__ emb,
                             float* __restrict__ out) {
    int t = blockIdx.x;
    int id = ids[t];
    const float4* src = (const float4*)(emb + (size_t)id * Hc);
    float4* dst = (float4*)(out + (size_t)t * Hc);
    dst[threadIdx.x] = src[threadIdx.x];
}

// ---------------- layernorm (half output) ----------------
__global__ void ln_kernel(const float* __restrict__ x,
                          const float* __restrict__ g,
                          const float* __restrict__ b,
                          __half* __restrict__ out) {
    __shared__ float s1[256], s2[256];
    int row = blockIdx.x, tid = threadIdx.x;
    float4 v = ((const float4*)(x + (size_t)row * Hc))[tid];
    s1[tid] = v.x + v.y + v.z + v.w;
    s2[tid] = v.x*v.x + v.y*v.y + v.z*v.z + v.w*v.w;
    __syncthreads();
    for (int s = 128; s > 0; s >>= 1) {
        if (tid < s) { s1[tid] += s1[tid+s]; s2[tid] += s2[tid+s]; }
        __syncthreads();
    }
    float mu  = s1[0] * (1.0f / Hc);
    float var = s2[0] * (1.0f / Hc) - mu * mu;
    float inv = rsqrtf(var + 1e-5f);
    float4 gg = ((const float4*)g)[tid];
    float4 bb = ((const float4*)b)[tid];
    __half2* op = (__half2*)(out + (size_t)row * Hc);
    op[2*tid]   = __floats2half2_rn((v.x - mu) * inv * gg.x + bb.x,
                                    (v.y - mu) * inv * gg.y + bb.y);
    op[2*tid+1] = __floats2half2_rn((v.z - mu) * inv * gg.z + bb.z,
                                    (v.w - mu) * inv * gg.w + bb.w);
}

// ---------------- fp16 tensor-core GEMM: C = act(A@Wt^T + bias) (+= residual C) ------
// Single __syncthreads per K-iter: wait -> sync -> prefetch(it+2) -> compute(it).
// Stage (it+2)%3 == (it-1)%3 is free because every thread finished compute(it-1)
// before this iteration's barrier.
template<bool RES, bool GELU_ACT, bool BIAS, bool OUT_HALF>
__global__ __launch_bounds__(256, 2)
void gemm_h(const __half* __restrict__ A, const __half* __restrict__ Wt,
            const float* __restrict__ bias, void* __restrict__ Cv,
            int N, int K) {
    extern __shared__ uint8_t dsm[];
    uint32_t smem = (uint32_t)__cvta_generic_to_shared(dsm);
    const uint32_t sA = smem;            // 3 stages x 16KB
    const uint32_t sB = smem + 49152;    // 3 stages x 16KB

    int tid = threadIdx.x, wid = tid >> 5, lane = tid & 31;
    int m0 = blockIdx.y * 128, n0 = blockIdx.x * 128;
    int warpM = (wid >> 2) * 64;
    int warpN = (wid & 3) * 32;
    int nIter = K >> 6;

    float acc[4][4][4];
    #pragma unroll
    for (int i = 0; i < 4; ++i)
        #pragma unroll
        for (int j = 0; j < 4; ++j)
            #pragma unroll
            for (int r = 0; r < 4; ++r) acc[i][j][r] = 0.f;

    int row = tid >> 1;
    int hseg = (tid & 1) * 32;
    const __half* ag = A  + (size_t)(m0 + row) * K + hseg;
    const __half* bg = Wt + (size_t)(n0 + row) * K + hseg;
    uint32_t so[4];
    #pragma unroll
    for (int i = 0; i < 4; ++i) {
        int c = (tid & 1) * 4 + i;
        so[i] = row * 128 + ((c ^ (row & 7)) << 4);
    }

    auto prefetch = [&](int it) {
        if (it < nIter) {
            uint32_t a_st = sA + (it % 3) * 16384;
            uint32_t b_st = sB + (it % 3) * 16384;
            const __half* ap = ag + (size_t)it * 64;
            const __half* bp = bg + (size_t)it * 64;
            #pragma unroll
            for (int i = 0; i < 4; ++i) cp16(a_st + so[i], ap + 8 * i);
            #pragma unroll
            for (int i = 0; i < 4; ++i) cp16(b_st + so[i], bp + 8 * i);
        }
        CP_COMMIT();
    };

    prefetch(0);
    prefetch(1);

    int lrow = lane & 15;
    int lchk = lane >> 4;

    for (int it = 0; it < nIter; ++it) {
        CP_WAIT1();
        __syncthreads();
        prefetch(it + 2);     // writes stage (it-1)%3 — free after the barrier
        uint32_t aBase = sA + (it % 3) * 16384;
        uint32_t bBase = sB + (it % 3) * 16384;
        #pragma unroll
        for (int ks = 0; ks < 4; ++ks) {
            uint32_t af[4][4], bf[2][4];
            #pragma unroll
            for (int mf = 0; mf < 4; ++mf) {
                int r = warpM + mf * 16 + lrow;
                int c = ks * 2 + lchk;
                ldm_x4(af[mf], aBase + r * 128 + ((c ^ (r & 7)) << 4));
            }
            #pragma unroll
            for (int g = 0; g < 2; ++g) {
                int r = warpN + g * 16 + lrow;
                int c = ks * 2 + lchk;
                ldm_x4(bf[g], bBase + r * 128 + ((c ^ (r & 7)) << 4));
            }
            #pragma unroll
            for (int mf = 0; mf < 4; ++mf) {
                mma_f16(acc[mf][0], af[mf], bf[0][0], bf[0][2]);
                mma_f16(acc[mf][1], af[mf], bf[0][1], bf[0][3]);
                mma_f16(acc[mf][2], af[mf], bf[1][0], bf[1][2]);
                mma_f16(acc[mf][3], af[mf], bf[1][1], bf[1][3]);
            }
        }
    }

    int rbase = m0 + warpM + (lane >> 2);
    int cbase = n0 + warpN + (lane & 3) * 2;
    #pragma unroll
    for (int mf = 0; mf < 4; ++mf) {
        #pragma unroll
        for (int nf = 0; nf < 4; ++nf) {
            int c = cbase + nf * 8;
            float bx = 0.f, by = 0.f;
            if (BIAS) { bx = bias[c]; by = bias[c + 1]; }
            #pragma unroll
            for (int half_ = 0; half_ < 2; ++half_) {
                int r = rbase + mf * 16 + half_ * 8;
                float v0 = acc[mf][nf][half_ * 2 + 0] + bx;
                float v1 = acc[mf][nf][half_ * 2 + 1] + by;
                if (GELU_ACT) { v0 = gelu_f(v0); v1 = gelu_f(v1); }
                if (OUT_HALF) {
                    __half2* cp = (__half2*)((__half*)Cv + (size_t)r * N + c);
                    *cp = __floats2half2_rn(v0, v1);
                } else {
                    float2* cp = (float2*)((float*)Cv + (size_t)r * N + c);
                    if (RES) { float2 old = *cp; v0 += old.x; v1 += old.y; }
                    float2 o; o.x = v0; o.y = v1;
                    *cp = o;
                }
            }
        }
    }
}

// ---------------- fused flash attention ----------------
// grid: (S/128, B*NH); 256 threads (8 warps x 16 rows). K/V 64-row tiles, double buffered.
__global__ __launch_bounds__(256)
void flash_kernel(const __half* __restrict__ qkvh, const int* __restrict__ sp,
                  __half* __restrict__ out) {
    __shared__ __align__(128) uint8_t sm[49152];
    uint32_t S0 = (uint32_t)__cvta_generic_to_shared(sm);
    const uint32_t sQ = S0;
    int tid = threadIdx.x, w = tid >> 5, lane = tid & 31;
    int i0 = blockIdx.x * 128;
    int bz = blockIdx.y;
    int b = bz >> 4, n = bz & 15;
    int spb = sp[b];
    float slope = exp2f(-0.5f * (float)(n + 1));

    const __half* qbase = qkvh + (size_t)b * Sc * 3 * Hc + n * 64;

    // Q tile 128x64 -> smem
    #pragma unroll
    for (int itr = 0; itr < 4; ++itr) {
        int id = itr * 256 + tid;
        int row = id >> 3, ch = id & 7;
        cp16(sQ + row * 128 + ((ch ^ (row & 7)) << 4),
             qbase + (size_t)(i0 + row) * 3 * Hc + ch * 8);
    }
    auto prefKV = [&](int jt) {
        int stage = jt & 1;
        uint32_t sK = S0 + 16384 + stage * 16384;
        uint32_t sV = sK + 8192;
        int j0 = jt * 64;
        #pragma unroll
        for (int itr = 0; itr < 2; ++itr) {
            int id = itr * 256 + tid;
            int row = id >> 3, ch = id & 7;
            uint32_t sw = row * 128 + ((ch ^ (row & 7)) << 4);
            const __half* g = qbase + (size_t)(j0 + row) * 3 * Hc + ch * 8;
            cp16(sK + sw, g + Hc);
            cp16(sV + sw, g + 2 * Hc);
        }
    };
    prefKV(0);
    CP_COMMIT();

    int jtmax = blockIdx.x * 2 + 1;
    int ibase = i0 + w * 16;
    int irow = ibase + (lane >> 2);
    int jcl = (lane & 3) * 2;

    float m_run[2] = {-1e30f, -1e30f};
    float l[2] = {0.f, 0.f};
    float co[8][4];
    #pragma unroll
    for (int i = 0; i < 8; ++i)
        #pragma unroll
        for (int j = 0; j < 4; ++j) co[i][j] = 0.f;
    uint32_t aq[4][4];
    bool qLoaded = false;

    for (int jt = 0; jt <= jtmax; ++jt) {
        bool hasNext = jt < jtmax;
        if (hasNext) { prefKV(jt + 1); CP_COMMIT(); }
        if (hasNext) { CP_WAIT1(); } else { CP_WAIT0(); }
        __syncthreads();
        int stage = jt & 1;
        uint32_t sK = S0 + 16384 + stage * 16384;
        uint32_t sV = sK + 8192;
        if (!qLoaded) {
            qLoaded = true;
            #pragma unroll
            for (int kc = 0; kc < 4; ++kc) {
                int r = w * 16 + (lane & 15);
                int c = kc * 2 + (lane >> 4);
                ldm_x4(aq[kc], sQ + r * 128 + ((c ^ (r & 7)) << 4));
            }
        }
        int j0 = jt * 64;
        if (j0 <= ibase + 15) {
            float c[8][4];
            #pragma unroll
            for (int i = 0; i < 8; ++i)
                #pragma unroll
                for (int j = 0; j < 4; ++j) c[i][j] = 0.f;
            // S = Q K^T
            #pragma unroll
            for (int kc = 0; kc < 4; ++kc) {
                uint32_t bf[4][4];
                #pragma unroll
                for (int g = 0; g < 4; ++g) {
                    int r = g * 16 + (lane & 15);
                    int cc = kc * 2 + (lane >> 4);
                    ldm_x4(bf[g], sK + r * 128 + ((cc ^ (r & 7)) << 4));
                }
                #pragma unroll
                for (int g = 0; g < 4; ++g) {
                    mma_f16(c[g * 2],     aq[kc], bf[g][0], bf[g][2]);
                    mma_f16(c[g * 2 + 1], aq[kc], bf[g][1], bf[g][3]);
                }
            }
            // mask + alibi
            float tmax[2] = {-1e30f, -1e30f};
            #pragma unroll
            for (int nf = 0; nf < 8; ++nf)
                #pragma unroll
                for (int rg = 0; rg < 4; ++rg) {
                    int i = irow + (rg >> 1) * 8;
                    int j = j0 + nf * 8 + jcl + (rg & 1);
                    bool ok = (j <= i) && !((i >= spb) && (j < spb));
                    float v = ok ? fmaf(c[nf][rg], 0.125f, -slope * (float)(i - j))
                                 : -1e9f;
                    c[nf][rg] = v;
                    tmax[rg >> 1] = fmaxf(tmax[rg >> 1], v);
                }
            float sfv[2];
            #pragma unroll
            for (int h = 0; h < 2; ++h) {
                tmax[h] = fmaxf(tmax[h], __shfl_xor_sync(0xffffffffu, tmax[h], 1));
                tmax[h] = fmaxf(tmax[h], __shfl_xor_sync(0xffffffffu, tmax[h], 2));
                float mn = fmaxf(m_run[h], tmax[h]);
                sfv[h] = __expf(m_run[h] - mn);
                m_run[h] = mn;
            }
            float rs[2] = {0.f, 0.f};
            #pragma unroll
            for (int nf = 0; nf < 8; ++nf)
                #pragma unroll
                for (int rg = 0; rg < 4; ++rg) {
                    float p = __expf(c[nf][rg] - m_run[rg >> 1]);
                    c[nf][rg] = p;
                    rs[rg >> 1] += p;
                }
            #pragma unroll
            for (int h = 0; h < 2; ++h) {
                rs[h] += __shfl_xor_sync(0xffffffffu, rs[h], 1);
                rs[h] += __shfl_xor_sync(0xffffffffu, rs[h], 2);
                l[h] = l[h] * sfv[h] + rs[h];
            }
            #pragma unroll
            for (int nf = 0; nf < 8; ++nf)
                #pragma unroll
                for (int rg = 0; rg < 4; ++rg) co[nf][rg] *= sfv[rg >> 1];
            // P fragments (register reshuffle)
            uint32_t ap[4][4];
            #pragma unroll
            for (int kc = 0; kc < 4; ++kc) {
                ap[kc][0] = pack_h2(c[2*kc][0],   c[2*kc][1]);
                ap[kc][1] = pack_h2(c[2*kc][2],   c[2*kc][3]);
                ap[kc][2] = pack_h2(c[2*kc+1][0], c[2*kc+1][1]);
                ap[kc][3] = pack_h2(c[2*kc+1][2], c[2*kc+1][3]);
            }
            // O += P V
            #pragma unroll
            for (int kc = 0; kc < 4; ++kc) {
                #pragma unroll
                for (int dp = 0; dp < 4; ++dp) {
                    uint32_t vf[4];
                    int r = kc * 16 + (lane & 15);
                    int cc = dp * 2 + (lane >> 4);
                    ldm_x4_t(vf, sV + r * 128 + ((cc ^ (r & 7)) << 4));
                    mma_f16(co[dp * 2],     ap[kc], vf[0], vf[1]);
                    mma_f16(co[dp * 2 + 1], ap[kc], vf[2], vf[3]);
                }
            }
        }
        __syncthreads();
    }

    float inv0 = 1.0f / l[0], inv1 = 1.0f / l[1];
    #pragma unroll
    for (int nf = 0; nf < 8; ++nf) {
        int cidx = n * 64 + nf * 8 + jcl;
        __half2* o0 = (__half2*)&out[(size_t)(b * Sc + irow) * Hc + cidx];
        *o0 = __floats2half2_rn(co[nf][0] * inv0, co[nf][1] * inv0);
        __half2* o1 = (__half2*)&out[(size_t)(b * Sc + irow + 8) * Hc + cidx];
        *o1 = __floats2half2_rn(co[nf][2] * inv1, co[nf][3] * inv1);
    }
}

// ---------------- launch ----------------
#define GEMM_SMEM 98304

extern "C" void kernel_launch(void* const* d_in, const int* in_sizes, int n_in,
                              void* d_out, int out_size) {
    const int*   ids    = (const int*)d_in[0];
    const int*   sp     = (const int*)d_in[1];
    const float* emb    = (const float*)d_in[2];
    const float* ln1_g  = (const float*)d_in[3];
    const float* ln1_b  = (const float*)d_in[4];
    const float* Wqkv   = (const float*)d_in[5];
    const float* bqkv   = (const float*)d_in[6];
    const float* Wo     = (const float*)d_in[7];
    const float* bo     = (const float*)d_in[8];
    const float* ln2_g  = (const float*)d_in[9];
    const float* ln2_b  = (const float*)d_in[10];
    const float* Wfc    = (const float*)d_in[11];
    const float* bfc    = (const float*)d_in[12];
    const float* Wproj  = (const float*)d_in[13];
    const float* bproj  = (const float*)d_in[14];
    const float* lnf_g  = (const float*)d_in[15];
    const float* lnf_b  = (const float*)d_in[16];
    float* out = (float*)d_out;

    float *x;
    __half *h, *qkvh, *attn, *ffn, *wT, *embH;
    cudaGetSymbolAddress((void**)&x,    g_x);
    cudaGetSymbolAddress((void**)&h,    g_h);
    cudaGetSymbolAddress((void**)&qkvh, g_qkvh);
    cudaGetSymbolAddress((void**)&attn, g_attn);
    cudaGetSymbolAddress((void**)&ffn,  g_ffn);
    cudaGetSymbolAddress((void**)&wT,   g_wT);
    cudaGetSymbolAddress((void**)&embH, g_embH);

    cudaFuncSetAttribute(gemm_h<false,false,true,true>,
                         cudaFuncAttributeMaxDynamicSharedMemorySize, GEMM_SMEM);
    cudaFuncSetAttribute(gemm_h<true,false,true,false>,
                         cudaFuncAttributeMaxDynamicSharedMemorySize, GEMM_SMEM);
    cudaFuncSetAttribute(gemm_h<false,true,true,true>,
                         cudaFuncAttributeMaxDynamicSharedMemorySize, GEMM_SMEM);
    cudaFuncSetAttribute(gemm_h<false,false,false,false>,
                         cudaFuncAttributeMaxDynamicSharedMemorySize, GEMM_SMEM);

    const size_t oQKV = 0;
    const size_t oWO  = (size_t)3*Hc*Hc;
    const size_t oFC  = oWO + (size_t)Hc*Hc;
    const size_t oPRJ = oFC + (size_t)Hc*Fc;

    dim3 tb(32, 8);
    for (int l = 0; l < NLc; ++l) {
        __half* base = wT + (size_t)l * LWT;
        transpose_half<<<dim3(3*Hc/32, Hc/32), tb>>>(Wqkv  + (size_t)l*Hc*3*Hc, base + oQKV, Hc, 3*Hc);
        transpose_half<<<dim3(Hc/32,   Hc/32), tb>>>(Wo    + (size_t)l*Hc*Hc,   base + oWO,  Hc, Hc);
        transpose_half<<<dim3(Fc/32,   Hc/32), tb>>>(Wfc   + (size_t)l*Hc*Fc,   base + oFC,  Hc, Fc);
        transpose_half<<<dim3(Hc/32,   Fc/32), tb>>>(Wproj + (size_t)l*Fc*Hc,   base + oPRJ, Fc, Hc);
    }
    half_copy<<<(Vc*Hc/4)/256, 256>>>(emb, embH);

    embed_kernel<<<Mrows, 256>>>(ids, emb, x);

    for (int l = 0; l < NLc; ++l) {
        __half* base = wT + (size_t)l * LWT;
        ln_kernel<<<Mrows, 256>>>(x, ln1_g + (size_t)l*Hc, ln1_b + (size_t)l*Hc, h);
        gemm_h<false,false,true,true><<<dim3(3*Hc/128, Mrows/128), 256, GEMM_SMEM>>>(
            h, base + oQKV, bqkv + (size_t)l*3*Hc, qkvh, 3*Hc, Hc);
        flash_kernel<<<dim3(Sc/128, Bc*NHc), 256>>>(qkvh, sp, attn);
        gemm_h<true,false,true,false><<<dim3(Hc/128, Mrows/128), 256, GEMM_SMEM>>>(
            attn, base + oWO, bo + (size_t)l*Hc, x, Hc, Hc);
        ln_kernel<<<Mrows, 256>>>(x, ln2_g + (size_t)l*Hc, ln2_b + (size_t)l*Hc, h);
        gemm_h<false,true,true,true><<<dim3(Fc/128, Mrows/128), 256, GEMM_SMEM>>>(
            h, base + oFC, bfc + (size_t)l*Fc, ffn, Fc, Hc);
        gemm_h<true,false,true,false><<<dim3(Hc/128, Mrows/128), 256, GEMM_SMEM>>>(
            ffn, base + oPRJ, bproj + (size_t)l*Hc, x, Hc, Fc);
    }

    ln_kernel<<<Mrows, 256>>>(x, lnf_g, lnf_b, h);
    gemm_h<false,false,false,false><<<dim3(Vc/128, Mrows/128), 256, GEMM_SMEM>>>(
        h, embH, nullptr, out, Vc, Hc);
}